// round 1
// baseline (speedup 1.0000x reference)
#include <cuda_runtime.h>
#include <math.h>

// ---------------- Problem constants ----------------
#define BB 8
#define SS 2048
#define EE 768
#define HH 3072          // R*E
#define MM (BB*SS)       // 16384
#define LN_EPS 1e-5f

// ---------------- Scratch (device globals; no allocs allowed) ----------------
__device__ float g_q[MM*EE];
__device__ float g_k[MM*EE];
__device__ float g_v[MM*EE];
__device__ float g_t[MM*EE];
__device__ float g_x1[MM*EE];
__device__ float g_x2[MM*EE];
__device__ float g_scores[(long long)BB*SS*SS];
__device__ float g_h[(long long)MM*HH];

// ---------------- Reductions ----------------
__device__ __forceinline__ float warpSum(float v) {
    #pragma unroll
    for (int o = 16; o > 0; o >>= 1) v += __shfl_xor_sync(0xffffffffu, v, o);
    return v;
}
__device__ __forceinline__ float warpMax(float v) {
    #pragma unroll
    for (int o = 16; o > 0; o >>= 1) v = fmaxf(v, __shfl_xor_sync(0xffffffffu, v, o));
    return v;
}
__device__ float blockSum(float v) {
    __shared__ float sh[32];
    int lane = threadIdx.x & 31, w = threadIdx.x >> 5;
    v = warpSum(v);
    if (lane == 0) sh[w] = v;
    __syncthreads();
    int nw = (blockDim.x + 31) >> 5;
    float r = (threadIdx.x < nw) ? sh[threadIdx.x] : 0.f;
    if (w == 0) r = warpSum(r);
    if (threadIdx.x == 0) sh[0] = r;
    __syncthreads();
    r = sh[0];
    __syncthreads();
    return r;
}
__device__ float blockMax(float v) {
    __shared__ float sh[32];
    int lane = threadIdx.x & 31, w = threadIdx.x >> 5;
    v = warpMax(v);
    if (lane == 0) sh[w] = v;
    __syncthreads();
    int nw = (blockDim.x + 31) >> 5;
    float r = (threadIdx.x < nw) ? sh[threadIdx.x] : -INFINITY;
    if (w == 0) r = warpMax(r);
    if (threadIdx.x == 0) sh[0] = r;
    __syncthreads();
    r = sh[0];
    __syncthreads();
    return r;
}

// ---------------- SGEMM NN: C = A[M,K] @ B[K,N] (+bias) (opt relu) ----------------
// BM=BN=128, BK=16, TM=TN=8, 256 threads. All dims are multiples of tile sizes.
// Batched via blockIdx.z with element strides sA,sB,sC (0 => shared operand).
// causalKlim: limits K to (blockIdx.y+1)*128 (P@V lower-triangular skip).
#define BM 128
#define BN 128
#define BK 16
#define TM 8
#define TN 8

__global__ __launch_bounds__(256, 2)
void sgemm_nn(const float* __restrict__ A, const float* __restrict__ B,
              const float* __restrict__ bias, float* __restrict__ C,
              int M, int N, int K,
              long long sA, long long sB, long long sC,
              int relu, int causalKlim)
{
    __shared__ float As[BK][BM + 4];
    __shared__ float Bs[BK][BN + 4];
    int z = blockIdx.z;
    A += (long long)z * sA;
    B += (long long)z * sB;
    C += (long long)z * sC;
    int rowStart = blockIdx.y * BM;
    int colStart = blockIdx.x * BN;
    int Keff = K;
    if (causalKlim) { int kl = rowStart + BM; if (kl < Keff) Keff = kl; }

    int tid = threadIdx.x;
    int aRow0 = tid >> 2;          // 0..63
    int aCol  = (tid & 3) * 4;     // 0,4,8,12
    int bRow0 = tid >> 5;          // 0..7
    int bCol  = (tid & 31) * 4;    // 0..124
    int tx = tid & 15, ty = tid >> 4;

    float acc[TM][TN] = {};
    float ra[TM], rb[TN];

    for (int kt = 0; kt < Keff; kt += BK) {
        #pragma unroll
        for (int r = 0; r < 2; r++) {
            int row = aRow0 + r * 64;
            float4 v = *reinterpret_cast<const float4*>(
                &A[(long long)(rowStart + row) * K + kt + aCol]);
            As[aCol + 0][row] = v.x;
            As[aCol + 1][row] = v.y;
            As[aCol + 2][row] = v.z;
            As[aCol + 3][row] = v.w;
        }
        #pragma unroll
        for (int r = 0; r < 2; r++) {
            int row = bRow0 + r * 8;
            *reinterpret_cast<float4*>(&Bs[row][bCol]) =
                *reinterpret_cast<const float4*>(
                    &B[(long long)(kt + row) * N + colStart + bCol]);
        }
        __syncthreads();
        #pragma unroll
        for (int k = 0; k < BK; k++) {
            #pragma unroll
            for (int m = 0; m < TM; m++) ra[m] = As[k][ty * TM + m];
            #pragma unroll
            for (int n = 0; n < TN; n++) rb[n] = Bs[k][tx * TN + n];
            #pragma unroll
            for (int m = 0; m < TM; m++)
                #pragma unroll
                for (int n = 0; n < TN; n++)
                    acc[m][n] += ra[m] * rb[n];
        }
        __syncthreads();
    }

    #pragma unroll
    for (int m = 0; m < TM; m++) {
        int row = rowStart + ty * TM + m;
        #pragma unroll
        for (int n = 0; n < TN; n += 4) {
            int col = colStart + tx * TN + n;
            float4 v;
            v.x = acc[m][n + 0]; v.y = acc[m][n + 1];
            v.z = acc[m][n + 2]; v.w = acc[m][n + 3];
            if (bias) {
                v.x += bias[col + 0]; v.y += bias[col + 1];
                v.z += bias[col + 2]; v.w += bias[col + 3];
            }
            if (relu) {
                v.x = fmaxf(v.x, 0.f); v.y = fmaxf(v.y, 0.f);
                v.z = fmaxf(v.z, 0.f); v.w = fmaxf(v.w, 0.f);
            }
            *reinterpret_cast<float4*>(&C[(long long)row * N + col]) = v;
        }
    }
}

// ---------------- SGEMM NT (scores): C = alpha * A[M,K] @ B[N,K]^T ----------------
// Batched over blockIdx.z. Causal: skip blocks entirely above the diagonal.
__global__ __launch_bounds__(256, 2)
void sgemm_nt(const float* __restrict__ A, const float* __restrict__ B,
              float* __restrict__ C,
              int M, int N, int K,
              long long sA, long long sB, long long sC,
              float alpha, int causal)
{
    int rowStart = blockIdx.y * BM;
    int colStart = blockIdx.x * BN;
    if (causal && (rowStart + BM - 1) < colStart) return;  // fully masked block

    __shared__ float As[BK][BM + 4];
    __shared__ float Bs[BK][BN + 4];
    int z = blockIdx.z;
    A += (long long)z * sA;
    B += (long long)z * sB;
    C += (long long)z * sC;

    int tid = threadIdx.x;
    int aRow0 = tid >> 2;
    int aCol  = (tid & 3) * 4;
    int tx = tid & 15, ty = tid >> 4;

    float acc[TM][TN] = {};
    float ra[TM], rb[TN];

    for (int kt = 0; kt < K; kt += BK) {
        #pragma unroll
        for (int r = 0; r < 2; r++) {
            int row = aRow0 + r * 64;
            float4 v = *reinterpret_cast<const float4*>(
                &A[(long long)(rowStart + row) * K + kt + aCol]);
            As[aCol + 0][row] = v.x;
            As[aCol + 1][row] = v.y;
            As[aCol + 2][row] = v.z;
            As[aCol + 3][row] = v.w;
        }
        #pragma unroll
        for (int r = 0; r < 2; r++) {
            int col = aRow0 + r * 64;   // key index j within tile
            float4 v = *reinterpret_cast<const float4*>(
                &B[(long long)(colStart + col) * K + kt + aCol]);
            Bs[aCol + 0][col] = v.x;
            Bs[aCol + 1][col] = v.y;
            Bs[aCol + 2][col] = v.z;
            Bs[aCol + 3][col] = v.w;
        }
        __syncthreads();
        #pragma unroll
        for (int k = 0; k < BK; k++) {
            #pragma unroll
            for (int m = 0; m < TM; m++) ra[m] = As[k][ty * TM + m];
            #pragma unroll
            for (int n = 0; n < TN; n++) rb[n] = Bs[k][tx * TN + n];
            #pragma unroll
            for (int m = 0; m < TM; m++)
                #pragma unroll
                for (int n = 0; n < TN; n++)
                    acc[m][n] += ra[m] * rb[n];
        }
        __syncthreads();
    }

    #pragma unroll
    for (int m = 0; m < TM; m++) {
        int row = rowStart + ty * TM + m;
        #pragma unroll
        for (int n = 0; n < TN; n += 4) {
            int col = colStart + tx * TN + n;
            float4 v;
            v.x = acc[m][n + 0] * alpha; v.y = acc[m][n + 1] * alpha;
            v.z = acc[m][n + 2] * alpha; v.w = acc[m][n + 3] * alpha;
            *reinterpret_cast<float4*>(&C[(long long)row * N + col]) = v;
        }
    }
}

// ---------------- Softmax over rows (causal: len=i+1, zero-fill tail) ----------------
__global__ void softmax_rows(float* __restrict__ P, int S, int causal)
{
    long long z = blockIdx.y;
    int i = blockIdx.x;
    float* row = P + (z * S + i) * (long long)S;
    int len = causal ? (i + 1) : S;

    float m = -INFINITY;
    for (int j = threadIdx.x; j < len; j += blockDim.x) m = fmaxf(m, row[j]);
    m = blockMax(m);

    float sum = 0.f;
    for (int j = threadIdx.x; j < len; j += blockDim.x) {
        float e = expf(row[j] - m);
        row[j] = e;
        sum += e;
    }
    sum = blockSum(sum);
    float inv = 1.f / sum;
    for (int j = threadIdx.x; j < len; j += blockDim.x) row[j] *= inv;
    for (int j = len + threadIdx.x; j < S; j += blockDim.x) row[j] = 0.f;
}

// ---------------- Fused residual-add + LayerNorm (E=768, 256 threads) ----------------
__global__ void add_ln(const float* __restrict__ X, const float* __restrict__ Hh,
                       const float* __restrict__ g, const float* __restrict__ b,
                       float* __restrict__ Y)
{
    long long row = blockIdx.x;
    const float* x = X + row * EE;
    const float* h = Hh + row * EE;
    float* y = Y + row * EE;
    int tid = threadIdx.x;

    float v[3];
    float s = 0.f;
    #pragma unroll
    for (int k = 0; k < 3; k++) {
        int c = tid + k * 256;
        v[k] = x[c] + h[c];
        s += v[k];
    }
    s = blockSum(s);
    float mean = s * (1.0f / EE);

    float q = 0.f;
    #pragma unroll
    for (int k = 0; k < 3; k++) { float d = v[k] - mean; q += d * d; }
    q = blockSum(q);
    float inv = rsqrtf(q * (1.0f / EE) + LN_EPS);

    #pragma unroll
    for (int k = 0; k < 3; k++) {
        int c = tid + k * 256;
        y[c] = (v[k] - mean) * inv * g[c] + b[c];
    }
}

// ---------------- Orchestration ----------------
extern "C" void kernel_launch(void* const* d_in, const int* in_sizes, int n_in,
                              void* d_out, int out_size)
{
    const float* x     = (const float*)d_in[0];
    const float* kv    = (const float*)d_in[1];
    const float* wq_w  = (const float*)d_in[2];
    const float* wq_b  = (const float*)d_in[3];
    const float* wk_w  = (const float*)d_in[4];
    const float* wk_b  = (const float*)d_in[5];
    const float* wv_w  = (const float*)d_in[6];
    const float* wv_b  = (const float*)d_in[7];
    const float* ln1_g = (const float*)d_in[8];
    const float* ln1_b = (const float*)d_in[9];
    const float* wq2_w = (const float*)d_in[10];
    const float* wq2_b = (const float*)d_in[11];
    const float* wk2_w = (const float*)d_in[12];
    const float* wk2_b = (const float*)d_in[13];
    const float* wv2_w = (const float*)d_in[14];
    const float* wv2_b = (const float*)d_in[15];
    const float* ln2_g = (const float*)d_in[16];
    const float* ln2_b = (const float*)d_in[17];
    const float* mlp_w1= (const float*)d_in[18];
    const float* mlp_b1= (const float*)d_in[19];
    const float* mlp_w2= (const float*)d_in[20];
    const float* mlp_b2= (const float*)d_in[21];
    const float* ln3_g = (const float*)d_in[22];
    const float* ln3_b = (const float*)d_in[23];
    float* out = (float*)d_out;

    float *q, *k, *v, *t, *x1, *x2, *sc, *hh;
    cudaGetSymbolAddress((void**)&q,  g_q);
    cudaGetSymbolAddress((void**)&k,  g_k);
    cudaGetSymbolAddress((void**)&v,  g_v);
    cudaGetSymbolAddress((void**)&t,  g_t);
    cudaGetSymbolAddress((void**)&x1, g_x1);
    cudaGetSymbolAddress((void**)&x2, g_x2);
    cudaGetSymbolAddress((void**)&sc, g_scores);
    cudaGetSymbolAddress((void**)&hh, g_h);

    const float scale = 1.0f / sqrtf((float)EE);
    dim3 blk(256);
    dim3 gProj(EE / BN, MM / BM, 1);       // (6,128)
    dim3 gMlp1(HH / BN, MM / BM, 1);       // (24,128)
    dim3 gScore(SS / BN, SS / BM, BB);     // (16,16,8)
    dim3 gPV(EE / BN, SS / BM, BB);        // (6,16,8)
    dim3 gSm(SS, BB);
    dim3 gLn(MM);

    // --- causal self-attention ---
    sgemm_nn<<<gProj, blk>>>(x, wq_w, wq_b, q, MM, EE, EE, 0, 0, 0, 0, 0);
    sgemm_nn<<<gProj, blk>>>(x, wk_w, wk_b, k, MM, EE, EE, 0, 0, 0, 0, 0);
    sgemm_nn<<<gProj, blk>>>(x, wv_w, wv_b, v, MM, EE, EE, 0, 0, 0, 0, 0);
    sgemm_nt<<<gScore, blk>>>(q, k, sc, SS, SS, EE,
                              (long long)SS * EE, (long long)SS * EE,
                              (long long)SS * SS, scale, 1);
    softmax_rows<<<gSm, blk>>>(sc, SS, 1);
    sgemm_nn<<<gPV, blk>>>(sc, v, nullptr, t, SS, EE, SS,
                           (long long)SS * SS, (long long)SS * EE,
                           (long long)SS * EE, 0, 1);
    add_ln<<<gLn, blk>>>(x, t, ln1_g, ln1_b, x1);

    // --- cross-attention ---
    sgemm_nn<<<gProj, blk>>>(x1, wq2_w, wq2_b, q, MM, EE, EE, 0, 0, 0, 0, 0);
    sgemm_nn<<<gProj, blk>>>(kv, wk2_w, wk2_b, k, MM, EE, EE, 0, 0, 0, 0, 0);
    sgemm_nn<<<gProj, blk>>>(kv, wv2_w, wv2_b, v, MM, EE, EE, 0, 0, 0, 0, 0);
    sgemm_nt<<<gScore, blk>>>(q, k, sc, SS, SS, EE,
                              (long long)SS * EE, (long long)SS * EE,
                              (long long)SS * SS, scale, 0);
    softmax_rows<<<gSm, blk>>>(sc, SS, 0);
    sgemm_nn<<<gPV, blk>>>(sc, v, nullptr, t, SS, EE, SS,
                           (long long)SS * SS, (long long)SS * EE,
                           (long long)SS * EE, 0, 0);
    add_ln<<<gLn, blk>>>(x1, t, ln2_g, ln2_b, x2);

    // --- MLP (ReLU after both linears) ---
    sgemm_nn<<<gMlp1, blk>>>(x2, mlp_w1, mlp_b1, hh, MM, HH, EE, 0, 0, 0, 1, 0);
    sgemm_nn<<<gProj, blk>>>(hh, mlp_w2, mlp_b2, t, MM, EE, HH, 0, 0, 0, 1, 0);
    add_ln<<<gLn, blk>>>(x2, t, ln3_g, ln3_b, out);
}

// round 3
// speedup vs baseline: 2.3526x; 2.3526x over previous
#include <cuda_runtime.h>
#include <math.h>
#include <stdint.h>

// ---------------- Problem constants ----------------
#define BB 8
#define SS 2048
#define EE 768
#define HH 3072          // R*E
#define MM (BB*SS)       // 16384
#define LN_EPS 1e-5f

// ---------------- Scratch (device globals; no allocs allowed) ----------------
__device__ float g_q[MM*EE];
__device__ float g_k[MM*EE];
__device__ float g_v[MM*EE];
__device__ float g_t[MM*EE];
__device__ float g_x1[MM*EE];
__device__ float g_x2[MM*EE];
__device__ float g_scores[(long long)BB*SS*SS];
__device__ float g_h[(long long)MM*HH];

// ---------------- Reductions ----------------
__device__ __forceinline__ float warpSum(float v) {
    #pragma unroll
    for (int o = 16; o > 0; o >>= 1) v += __shfl_xor_sync(0xffffffffu, v, o);
    return v;
}
__device__ __forceinline__ float warpMax(float v) {
    #pragma unroll
    for (int o = 16; o > 0; o >>= 1) v = fmaxf(v, __shfl_xor_sync(0xffffffffu, v, o));
    return v;
}
__device__ float blockSum(float v) {
    __shared__ float sh[32];
    int lane = threadIdx.x & 31, w = threadIdx.x >> 5;
    v = warpSum(v);
    if (lane == 0) sh[w] = v;
    __syncthreads();
    int nw = (blockDim.x + 31) >> 5;
    float r = (threadIdx.x < nw) ? sh[threadIdx.x] : 0.f;
    if (w == 0) r = warpSum(r);
    if (threadIdx.x == 0) sh[0] = r;
    __syncthreads();
    r = sh[0];
    __syncthreads();
    return r;
}
__device__ float blockMax(float v) {
    __shared__ float sh[32];
    int lane = threadIdx.x & 31, w = threadIdx.x >> 5;
    v = warpMax(v);
    if (lane == 0) sh[w] = v;
    __syncthreads();
    int nw = (blockDim.x + 31) >> 5;
    float r = (threadIdx.x < nw) ? sh[threadIdx.x] : -INFINITY;
    if (w == 0) r = warpMax(r);
    if (threadIdx.x == 0) sh[0] = r;
    __syncthreads();
    r = sh[0];
    __syncthreads();
    return r;
}

// ---------------- TF32 helpers ----------------
__device__ __forceinline__ uint32_t f2tf(float x) {
    uint32_t r;
    asm("cvt.rna.tf32.f32 %0, %1;" : "=r"(r) : "f"(x));
    return r;
}
__device__ __forceinline__ void mma_tf32(float* d, const uint32_t* a,
                                         const uint32_t* b, const float* c) {
    asm volatile(
        "mma.sync.aligned.m16n8k8.row.col.f32.tf32.tf32.f32 "
        "{%0,%1,%2,%3}, {%4,%5,%6,%7}, {%8,%9}, {%10,%11,%12,%13};\n"
        : "=f"(d[0]), "=f"(d[1]), "=f"(d[2]), "=f"(d[3])
        : "r"(a[0]), "r"(a[1]), "r"(a[2]), "r"(a[3]),
          "r"(b[0]), "r"(b[1]),
          "f"(c[0]), "f"(c[1]), "f"(c[2]), "f"(c[3]));
}

// ---------------- TF32 MMA GEMM: CTA 128x128, BK=32, 4 warps of 64x64 ----------------
// Smem layout: k-major [k][m] with row stride 136 -> frag loads are bank-conflict-free
// (addr = k*136 + m; lanes span 4 k-slices (4*8 bank offset) x 8 m (1..8) = 32 banks).
#define BKK 32
#define SMS 136

// ---- NN: C = A[M,K] @ B[K,N] (+bias) (opt relu). Batched via z strides.
// causalKlim limits K to rowStart+128 (P@V lower-triangular skip).
__global__ __launch_bounds__(128, 2)
void mma_nn(const float* __restrict__ A, const float* __restrict__ B,
            const float* __restrict__ bias, float* __restrict__ C,
            int M, int N, int K,
            long long sA, long long sB, long long sC,
            int relu, int causalKlim)
{
    __shared__ uint32_t As[BKK][SMS];
    __shared__ uint32_t Bs[BKK][SMS];
    int z = blockIdx.z;
    A += (long long)z * sA;
    B += (long long)z * sB;
    C += (long long)z * sC;
    int rowStart = blockIdx.y * 128;
    int colStart = blockIdx.x * 128;
    int Keff = K;
    if (causalKlim) { int kl = rowStart + 128; if (kl < Keff) Keff = kl; }

    int tid  = threadIdx.x;
    int lane = tid & 31, wid = tid >> 5;
    int wm = (wid >> 1) * 64, wn = (wid & 1) * 64;
    int g = lane >> 2, tg = lane & 3;

    float acc[4][8][4] = {};

    for (int kt = 0; kt < Keff; kt += BKK) {
        // A tile: 128 m x 32 k
        #pragma unroll
        for (int i = 0; i < 8; i++) {
            int idx = tid + i * 128;
            int m = idx >> 3, kq = (idx & 7) * 4;
            float4 v = *reinterpret_cast<const float4*>(
                &A[(long long)(rowStart + m) * K + kt + kq]);
            As[kq + 0][m] = f2tf(v.x);
            As[kq + 1][m] = f2tf(v.y);
            As[kq + 2][m] = f2tf(v.z);
            As[kq + 3][m] = f2tf(v.w);
        }
        // B tile: 32 k x 128 n (already k-major in gmem)
        #pragma unroll
        for (int i = 0; i < 8; i++) {
            int idx = tid + i * 128;
            int k = idx >> 5, nq = (idx & 31) * 4;
            float4 v = *reinterpret_cast<const float4*>(
                &B[(long long)(kt + k) * N + colStart + nq]);
            uint4 u;
            u.x = f2tf(v.x); u.y = f2tf(v.y); u.z = f2tf(v.z); u.w = f2tf(v.w);
            *reinterpret_cast<uint4*>(&Bs[k][nq]) = u;
        }
        __syncthreads();

        #pragma unroll
        for (int ks = 0; ks < 4; ks++) {
            int k0 = ks * 8;
            uint32_t afr[4][4], bfr[8][2];
            #pragma unroll
            for (int mi = 0; mi < 4; mi++) {
                int r = wm + mi * 16 + g;
                afr[mi][0] = As[k0 + tg][r];
                afr[mi][1] = As[k0 + tg][r + 8];
                afr[mi][2] = As[k0 + tg + 4][r];
                afr[mi][3] = As[k0 + tg + 4][r + 8];
            }
            #pragma unroll
            for (int ni = 0; ni < 8; ni++) {
                int n = wn + ni * 8 + g;
                bfr[ni][0] = Bs[k0 + tg][n];
                bfr[ni][1] = Bs[k0 + tg + 4][n];
            }
            #pragma unroll
            for (int mi = 0; mi < 4; mi++)
                #pragma unroll
                for (int ni = 0; ni < 8; ni++)
                    mma_tf32(acc[mi][ni], afr[mi], bfr[ni], acc[mi][ni]);
        }
        __syncthreads();
    }

    // Epilogue
    #pragma unroll
    for (int mi = 0; mi < 4; mi++) {
        int row0 = rowStart + wm + mi * 16 + g;
        #pragma unroll
        for (int ni = 0; ni < 8; ni++) {
            int col = colStart + wn + ni * 8 + tg * 2;
            float2 v0, v1;
            v0.x = acc[mi][ni][0]; v0.y = acc[mi][ni][1];
            v1.x = acc[mi][ni][2]; v1.y = acc[mi][ni][3];
            if (bias) {
                float b0 = bias[col], b1 = bias[col + 1];
                v0.x += b0; v0.y += b1; v1.x += b0; v1.y += b1;
            }
            if (relu) {
                v0.x = fmaxf(v0.x, 0.f); v0.y = fmaxf(v0.y, 0.f);
                v1.x = fmaxf(v1.x, 0.f); v1.y = fmaxf(v1.y, 0.f);
            }
            *reinterpret_cast<float2*>(&C[(long long)row0 * N + col]) = v0;
            *reinterpret_cast<float2*>(&C[(long long)(row0 + 8) * N + col]) = v1;
        }
    }
}

// ---- NT (scores): C = alpha * A[M,K] @ B[N,K]^T. Causal: skip masked blocks.
__global__ __launch_bounds__(128, 2)
void mma_nt(const float* __restrict__ A, const float* __restrict__ B,
            float* __restrict__ C,
            int M, int N, int K,
            long long sA, long long sB, long long sC,
            float alpha, int causal)
{
    int rowStart = blockIdx.y * 128;
    int colStart = blockIdx.x * 128;
    if (causal && (rowStart + 128 - 1) < colStart) return;  // fully masked

    __shared__ uint32_t As[BKK][SMS];
    __shared__ uint32_t Bs[BKK][SMS];
    int z = blockIdx.z;
    A += (long long)z * sA;
    B += (long long)z * sB;
    C += (long long)z * sC;

    int tid  = threadIdx.x;
    int lane = tid & 31, wid = tid >> 5;
    int wm = (wid >> 1) * 64, wn = (wid & 1) * 64;
    int g = lane >> 2, tg = lane & 3;

    float acc[4][8][4] = {};

    for (int kt = 0; kt < K; kt += BKK) {
        #pragma unroll
        for (int i = 0; i < 8; i++) {
            int idx = tid + i * 128;
            int m = idx >> 3, kq = (idx & 7) * 4;
            float4 v = *reinterpret_cast<const float4*>(
                &A[(long long)(rowStart + m) * K + kt + kq]);
            As[kq + 0][m] = f2tf(v.x);
            As[kq + 1][m] = f2tf(v.y);
            As[kq + 2][m] = f2tf(v.z);
            As[kq + 3][m] = f2tf(v.w);
        }
        // B from Kmat [N,K] row-major: transpose into k-major smem
        #pragma unroll
        for (int i = 0; i < 8; i++) {
            int idx = tid + i * 128;
            int n = idx >> 3, kq = (idx & 7) * 4;
            float4 v = *reinterpret_cast<const float4*>(
                &B[(long long)(colStart + n) * K + kt + kq]);
            Bs[kq + 0][n] = f2tf(v.x);
            Bs[kq + 1][n] = f2tf(v.y);
            Bs[kq + 2][n] = f2tf(v.z);
            Bs[kq + 3][n] = f2tf(v.w);
        }
        __syncthreads();

        #pragma unroll
        for (int ks = 0; ks < 4; ks++) {
            int k0 = ks * 8;
            uint32_t afr[4][4], bfr[8][2];
            #pragma unroll
            for (int mi = 0; mi < 4; mi++) {
                int r = wm + mi * 16 + g;
                afr[mi][0] = As[k0 + tg][r];
                afr[mi][1] = As[k0 + tg][r + 8];
                afr[mi][2] = As[k0 + tg + 4][r];
                afr[mi][3] = As[k0 + tg + 4][r + 8];
            }
            #pragma unroll
            for (int ni = 0; ni < 8; ni++) {
                int n = wn + ni * 8 + g;
                bfr[ni][0] = Bs[k0 + tg][n];
                bfr[ni][1] = Bs[k0 + tg + 4][n];
            }
            #pragma unroll
            for (int mi = 0; mi < 4; mi++)
                #pragma unroll
                for (int ni = 0; ni < 8; ni++)
                    mma_tf32(acc[mi][ni], afr[mi], bfr[ni], acc[mi][ni]);
        }
        __syncthreads();
    }

    #pragma unroll
    for (int mi = 0; mi < 4; mi++) {
        int row0 = rowStart + wm + mi * 16 + g;
        #pragma unroll
        for (int ni = 0; ni < 8; ni++) {
            int col = colStart + wn + ni * 8 + tg * 2;
            float2 v0, v1;
            v0.x = acc[mi][ni][0] * alpha; v0.y = acc[mi][ni][1] * alpha;
            v1.x = acc[mi][ni][2] * alpha; v1.y = acc[mi][ni][3] * alpha;
            *reinterpret_cast<float2*>(&C[(long long)row0 * N + col]) = v0;
            *reinterpret_cast<float2*>(&C[(long long)(row0 + 8) * N + col]) = v1;
        }
    }
}

// ---------------- Softmax over rows (causal: len=i+1, zero-fill tail) ----------------
__global__ void softmax_rows(float* __restrict__ P, int S, int causal)
{
    long long z = blockIdx.y;
    int i = blockIdx.x;
    float* row = P + (z * S + i) * (long long)S;
    int len = causal ? (i + 1) : S;

    float m = -INFINITY;
    for (int j = threadIdx.x; j < len; j += blockDim.x) m = fmaxf(m, row[j]);
    m = blockMax(m);

    float sum = 0.f;
    for (int j = threadIdx.x; j < len; j += blockDim.x) {
        float e = expf(row[j] - m);
        row[j] = e;
        sum += e;
    }
    sum = blockSum(sum);
    float inv = 1.f / sum;
    for (int j = threadIdx.x; j < len; j += blockDim.x) row[j] *= inv;
    for (int j = len + threadIdx.x; j < S; j += blockDim.x) row[j] = 0.f;
}

// ---------------- Fused residual-add + LayerNorm (E=768, 256 threads) ----------------
__global__ void add_ln(const float* __restrict__ X, const float* __restrict__ Hh,
                       const float* __restrict__ g, const float* __restrict__ b,
                       float* __restrict__ Y)
{
    long long row = blockIdx.x;
    const float* x = X + row * EE;
    const float* h = Hh + row * EE;
    float* y = Y + row * EE;
    int tid = threadIdx.x;

    float v[3];
    float s = 0.f;
    #pragma unroll
    for (int k = 0; k < 3; k++) {
        int c = tid + k * 256;
        v[k] = x[c] + h[c];
        s += v[k];
    }
    s = blockSum(s);
    float mean = s * (1.0f / EE);

    float q = 0.f;
    #pragma unroll
    for (int k = 0; k < 3; k++) { float d = v[k] - mean; q += d * d; }
    q = blockSum(q);
    float inv = rsqrtf(q * (1.0f / EE) + LN_EPS);

    #pragma unroll
    for (int k = 0; k < 3; k++) {
        int c = tid + k * 256;
        y[c] = (v[k] - mean) * inv * g[c] + b[c];
    }
}

// ---------------- Orchestration ----------------
extern "C" void kernel_launch(void* const* d_in, const int* in_sizes, int n_in,
                              void* d_out, int out_size)
{
    const float* x     = (const float*)d_in[0];
    const float* kv    = (const float*)d_in[1];
    const float* wq_w  = (const float*)d_in[2];
    const float* wq_b  = (const float*)d_in[3];
    const float* wk_w  = (const float*)d_in[4];
    const float* wk_b  = (const float*)d_in[5];
    const float* wv_w  = (const float*)d_in[6];
    const float* wv_b  = (const float*)d_in[7];
    const float* ln1_g = (const float*)d_in[8];
    const float* ln1_b = (const float*)d_in[9];
    const float* wq2_w = (const float*)d_in[10];
    const float* wq2_b = (const float*)d_in[11];
    const float* wk2_w = (const float*)d_in[12];
    const float* wk2_b = (const float*)d_in[13];
    const float* wv2_w = (const float*)d_in[14];
    const float* wv2_b = (const float*)d_in[15];
    const float* ln2_g = (const float*)d_in[16];
    const float* ln2_b = (const float*)d_in[17];
    const float* mlp_w1= (const float*)d_in[18];
    const float* mlp_b1= (const float*)d_in[19];
    const float* mlp_w2= (const float*)d_in[20];
    const float* mlp_b2= (const float*)d_in[21];
    const float* ln3_g = (const float*)d_in[22];
    const float* ln3_b = (const float*)d_in[23];
    float* out = (float*)d_out;

    float *q, *k, *v, *t, *x1, *x2, *sc, *hh;
    cudaGetSymbolAddress((void**)&q,  g_q);
    cudaGetSymbolAddress((void**)&k,  g_k);
    cudaGetSymbolAddress((void**)&v,  g_v);
    cudaGetSymbolAddress((void**)&t,  g_t);
    cudaGetSymbolAddress((void**)&x1, g_x1);
    cudaGetSymbolAddress((void**)&x2, g_x2);
    cudaGetSymbolAddress((void**)&sc, g_scores);
    cudaGetSymbolAddress((void**)&hh, g_h);

    const float scale = 1.0f / sqrtf((float)EE);
    dim3 blk(128);
    dim3 blk256(256);
    dim3 gProj(EE / 128, MM / 128, 1);       // (6,128)
    dim3 gMlp1(HH / 128, MM / 128, 1);       // (24,128)
    dim3 gScore(SS / 128, SS / 128, BB);     // (16,16,8)
    dim3 gPV(EE / 128, SS / 128, BB);        // (6,16,8)
    dim3 gSm(SS, BB);
    dim3 gLn(MM);

    // --- causal self-attention ---
    mma_nn<<<gProj, blk>>>(x, wq_w, wq_b, q, MM, EE, EE, 0, 0, 0, 0, 0);
    mma_nn<<<gProj, blk>>>(x, wk_w, wk_b, k, MM, EE, EE, 0, 0, 0, 0, 0);
    mma_nn<<<gProj, blk>>>(x, wv_w, wv_b, v, MM, EE, EE, 0, 0, 0, 0, 0);
    mma_nt<<<gScore, blk>>>(q, k, sc, SS, SS, EE,
                            (long long)SS * EE, (long long)SS * EE,
                            (long long)SS * SS, scale, 1);
    softmax_rows<<<gSm, blk256>>>(sc, SS, 1);
    mma_nn<<<gPV, blk>>>(sc, v, nullptr, t, SS, EE, SS,
                         (long long)SS * SS, (long long)SS * EE,
                         (long long)SS * EE, 0, 1);
    add_ln<<<gLn, blk256>>>(x, t, ln1_g, ln1_b, x1);

    // --- cross-attention ---
    mma_nn<<<gProj, blk>>>(x1, wq2_w, wq2_b, q, MM, EE, EE, 0, 0, 0, 0, 0);
    mma_nn<<<gProj, blk>>>(kv, wk2_w, wk2_b, k, MM, EE, EE, 0, 0, 0, 0, 0);
    mma_nn<<<gProj, blk>>>(kv, wv2_w, wv2_b, v, MM, EE, EE, 0, 0, 0, 0, 0);
    mma_nt<<<gScore, blk>>>(q, k, sc, SS, SS, EE,
                            (long long)SS * EE, (long long)SS * EE,
                            (long long)SS * SS, scale, 0);
    softmax_rows<<<gSm, blk256>>>(sc, SS, 0);
    mma_nn<<<gPV, blk>>>(sc, v, nullptr, t, SS, EE, SS,
                         (long long)SS * SS, (long long)SS * EE,
                         (long long)SS * EE, 0, 0);
    add_ln<<<gLn, blk256>>>(x1, t, ln2_g, ln2_b, x2);

    // --- MLP (ReLU after both linears) ---
    mma_nn<<<gMlp1, blk>>>(x2, mlp_w1, mlp_b1, hh, MM, HH, EE, 0, 0, 0, 1, 0);
    mma_nn<<<gProj, blk>>>(hh, mlp_w2, mlp_b2, t, MM, EE, HH, 0, 0, 0, 1, 0);
    add_ln<<<gLn, blk256>>>(x2, t, ln3_g, ln3_b, out);
}

// round 5
// speedup vs baseline: 3.1123x; 1.3230x over previous
#include <cuda_runtime.h>
#include <math.h>
#include <stdint.h>

// ---------------- Problem constants ----------------
#define BB 8
#define SS 2048
#define EE 768
#define HH 3072          // R*E
#define MM (BB*SS)       // 16384
#define LN_EPS 1e-5f

// ---------------- Scratch (device globals; no allocs allowed) ----------------
__device__ float g_q[MM*EE];
__device__ float g_k[MM*EE];
__device__ float g_v[MM*EE];
__device__ float g_t[MM*EE];
__device__ float g_x1[MM*EE];
__device__ float g_x2[MM*EE];
__device__ float g_scores[(long long)BB*SS*SS];
__device__ float g_h[(long long)MM*HH];

// ---------------- Reductions ----------------
__device__ __forceinline__ float warpSum(float v) {
    #pragma unroll
    for (int o = 16; o > 0; o >>= 1) v += __shfl_xor_sync(0xffffffffu, v, o);
    return v;
}
__device__ __forceinline__ float warpMax(float v) {
    #pragma unroll
    for (int o = 16; o > 0; o >>= 1) v = fmaxf(v, __shfl_xor_sync(0xffffffffu, v, o));
    return v;
}
__device__ float blockSum(float v) {
    __shared__ float sh[32];
    int lane = threadIdx.x & 31, w = threadIdx.x >> 5;
    v = warpSum(v);
    if (lane == 0) sh[w] = v;
    __syncthreads();
    int nw = (blockDim.x + 31) >> 5;
    float r = (threadIdx.x < nw) ? sh[threadIdx.x] : 0.f;
    if (w == 0) r = warpSum(r);
    if (threadIdx.x == 0) sh[0] = r;
    __syncthreads();
    r = sh[0];
    __syncthreads();
    return r;
}
__device__ float blockMax(float v) {
    __shared__ float sh[32];
    int lane = threadIdx.x & 31, w = threadIdx.x >> 5;
    v = warpMax(v);
    if (lane == 0) sh[w] = v;
    __syncthreads();
    int nw = (blockDim.x + 31) >> 5;
    float r = (threadIdx.x < nw) ? sh[threadIdx.x] : -INFINITY;
    if (w == 0) r = warpMax(r);
    if (threadIdx.x == 0) sh[0] = r;
    __syncthreads();
    r = sh[0];
    __syncthreads();
    return r;
}

// ---------------- MMA / cp.async helpers ----------------
// NOTE: tf32 mma reads only the top 19 bits of each 32-bit operand register,
// so raw fp32 bits are a valid (truncated) tf32 operand. No cvt needed.
__device__ __forceinline__ void mma_tf32(float* d, const uint32_t* a,
                                         const uint32_t* b, const float* c) {
    asm volatile(
        "mma.sync.aligned.m16n8k8.row.col.f32.tf32.tf32.f32 "
        "{%0,%1,%2,%3}, {%4,%5,%6,%7}, {%8,%9}, {%10,%11,%12,%13};\n"
        : "=f"(d[0]), "=f"(d[1]), "=f"(d[2]), "=f"(d[3])
        : "r"(a[0]), "r"(a[1]), "r"(a[2]), "r"(a[3]),
          "r"(b[0]), "r"(b[1]),
          "f"(c[0]), "f"(c[1]), "f"(c[2]), "f"(c[3]));
}
__device__ __forceinline__ void cp16(uint32_t dst, const void* src) {
    asm volatile("cp.async.cg.shared.global [%0], [%1], 16;\n" :: "r"(dst), "l"(src));
}
__device__ __forceinline__ void cp_commit() {
    asm volatile("cp.async.commit_group;\n");
}
__device__ __forceinline__ void cp_wait0() {
    asm volatile("cp.async.wait_group 0;\n");
}
__device__ __forceinline__ void cp_wait1() {
    asm volatile("cp.async.wait_group 1;\n");
}

// ---------------- TF32 GEMM: CTA 128x128, BK=16, 256 thr, 8 warps of 64x32 ----------------
// A smem: m-major, stride 20 floats (frag reads hit 32 distinct banks: (20m+tg)%32).
// B smem (NN): k-major, stride 136 (reads (8*tg+g)%32 distinct banks).
// 2-stage cp.async double buffer.
#define BK2 16
#define ASTR 20
#define BSTR 136
#define A_ELE (128*ASTR)   // 2560 floats per stage
#define B_ELE (BK2*BSTR)   // 2176 floats per stage

// ---- NN: C = A[M,K] @ B[K,N] (+bias) (opt relu). Batched via z strides.
__global__ __launch_bounds__(256, 2)
void mma_nn(const float* __restrict__ A, const float* __restrict__ B,
            const float* __restrict__ bias, float* __restrict__ C,
            int M, int N, int K,
            long long sA, long long sB, long long sC,
            int relu, int causalKlim)
{
    __shared__ uint32_t As[2][A_ELE];
    __shared__ uint32_t Bs[2][B_ELE];
    int z = blockIdx.z;
    A += (long long)z * sA;
    B += (long long)z * sB;
    C += (long long)z * sC;
    int rowStart = blockIdx.y * 128;
    int colStart = blockIdx.x * 128;
    int Keff = K;
    if (causalKlim) { int kl = rowStart + 128; if (kl < Keff) Keff = kl; }
    int ntiles = Keff / BK2;

    int tid  = threadIdx.x;
    int lane = tid & 31, wid = tid >> 5;
    int wm = (wid >> 2) * 64, wn = (wid & 3) * 32;
    int g = lane >> 2, tg = lane & 3;

    uint32_t asBase = (uint32_t)__cvta_generic_to_shared(&As[0][0]);
    uint32_t bsBase = (uint32_t)__cvta_generic_to_shared(&Bs[0][0]);

    // per-thread load coords (2 x 16B each for A and B)
    int amA[2], akA[2];
    int bkB[2], bnB[2];
    #pragma unroll
    for (int i = 0; i < 2; i++) {
        int f = tid + i * 256;
        amA[i] = f >> 2; akA[i] = (f & 3) * 4;
        bkB[i] = f >> 5; bnB[i] = (f & 31) * 4;
    }

    auto loadTile = [&](int kt, int s) {
        #pragma unroll
        for (int i = 0; i < 2; i++) {
            cp16(asBase + (s * A_ELE + amA[i] * ASTR + akA[i]) * 4,
                 &A[(long long)(rowStart + amA[i]) * K + kt + akA[i]]);
        }
        #pragma unroll
        for (int i = 0; i < 2; i++) {
            cp16(bsBase + (s * B_ELE + bkB[i] * BSTR + bnB[i]) * 4,
                 &B[(long long)(kt + bkB[i]) * N + colStart + bnB[i]]);
        }
        cp_commit();
    };

    float acc[4][4][4] = {};

    loadTile(0, 0);
    int buf = 0;
    for (int it = 0; it < ntiles; it++) {
        if (it + 1 < ntiles) { loadTile((it + 1) * BK2, buf ^ 1); cp_wait1(); }
        else cp_wait0();
        __syncthreads();

        const uint32_t* as = &As[buf][0];
        const uint32_t* bs = &Bs[buf][0];
        #pragma unroll
        for (int ks = 0; ks < 2; ks++) {
            int k0 = ks * 8;
            uint32_t afr[4][4], bfr[4][2];
            #pragma unroll
            for (int mi = 0; mi < 4; mi++) {
                int r = wm + mi * 16 + g;
                afr[mi][0] = as[r * ASTR + k0 + tg];
                afr[mi][1] = as[(r + 8) * ASTR + k0 + tg];
                afr[mi][2] = as[r * ASTR + k0 + tg + 4];
                afr[mi][3] = as[(r + 8) * ASTR + k0 + tg + 4];
            }
            #pragma unroll
            for (int ni = 0; ni < 4; ni++) {
                int n = wn + ni * 8 + g;
                bfr[ni][0] = bs[(k0 + tg) * BSTR + n];
                bfr[ni][1] = bs[(k0 + tg + 4) * BSTR + n];
            }
            #pragma unroll
            for (int mi = 0; mi < 4; mi++)
                #pragma unroll
                for (int ni = 0; ni < 4; ni++)
                    mma_tf32(acc[mi][ni], afr[mi], bfr[ni], acc[mi][ni]);
        }
        __syncthreads();
        buf ^= 1;
    }

    // Epilogue
    #pragma unroll
    for (int mi = 0; mi < 4; mi++) {
        int row0 = rowStart + wm + mi * 16 + g;
        #pragma unroll
        for (int ni = 0; ni < 4; ni++) {
            int col = colStart + wn + ni * 8 + tg * 2;
            float2 v0, v1;
            v0.x = acc[mi][ni][0]; v0.y = acc[mi][ni][1];
            v1.x = acc[mi][ni][2]; v1.y = acc[mi][ni][3];
            if (bias) {
                float b0 = bias[col], b1 = bias[col + 1];
                v0.x += b0; v0.y += b1; v1.x += b0; v1.y += b1;
            }
            if (relu) {
                v0.x = fmaxf(v0.x, 0.f); v0.y = fmaxf(v0.y, 0.f);
                v1.x = fmaxf(v1.x, 0.f); v1.y = fmaxf(v1.y, 0.f);
            }
            *reinterpret_cast<float2*>(&C[(long long)row0 * N + col]) = v0;
            *reinterpret_cast<float2*>(&C[(long long)(row0 + 8) * N + col]) = v1;
        }
    }
}

// ---- NT (scores): C = alpha * A[M,K] @ B[N,K]^T. Causal: skip masked blocks.
// Both operands row-major K-contiguous -> both use m-major stride-20 smem.
__global__ __launch_bounds__(256, 2)
void mma_nt(const float* __restrict__ A, const float* __restrict__ B,
            float* __restrict__ C,
            int M, int N, int K,
            long long sA, long long sB, long long sC,
            float alpha, int causal)
{
    int rowStart = blockIdx.y * 128;
    int colStart = blockIdx.x * 128;
    if (causal && (rowStart + 128 - 1) < colStart) return;  // fully masked

    __shared__ uint32_t As[2][A_ELE];
    __shared__ uint32_t Bs[2][A_ELE];
    int z = blockIdx.z;
    A += (long long)z * sA;
    B += (long long)z * sB;
    C += (long long)z * sC;
    int ntiles = K / BK2;

    int tid  = threadIdx.x;
    int lane = tid & 31, wid = tid >> 5;
    int wm = (wid >> 2) * 64, wn = (wid & 3) * 32;
    int g = lane >> 2, tg = lane & 3;

    uint32_t asBase = (uint32_t)__cvta_generic_to_shared(&As[0][0]);
    uint32_t bsBase = (uint32_t)__cvta_generic_to_shared(&Bs[0][0]);

    int am[2], ak[2];
    #pragma unroll
    for (int i = 0; i < 2; i++) {
        int f = tid + i * 256;
        am[i] = f >> 2; ak[i] = (f & 3) * 4;
    }

    auto loadTile = [&](int kt, int s) {
        #pragma unroll
        for (int i = 0; i < 2; i++) {
            cp16(asBase + (s * A_ELE + am[i] * ASTR + ak[i]) * 4,
                 &A[(long long)(rowStart + am[i]) * K + kt + ak[i]]);
        }
        #pragma unroll
        for (int i = 0; i < 2; i++) {
            cp16(bsBase + (s * A_ELE + am[i] * ASTR + ak[i]) * 4,
                 &B[(long long)(colStart + am[i]) * K + kt + ak[i]]);
        }
        cp_commit();
    };

    float acc[4][4][4] = {};

    loadTile(0, 0);
    int buf = 0;
    for (int it = 0; it < ntiles; it++) {
        if (it + 1 < ntiles) { loadTile((it + 1) * BK2, buf ^ 1); cp_wait1(); }
        else cp_wait0();
        __syncthreads();

        const uint32_t* as = &As[buf][0];
        const uint32_t* bs = &Bs[buf][0];
        #pragma unroll
        for (int ks = 0; ks < 2; ks++) {
            int k0 = ks * 8;
            uint32_t afr[4][4], bfr[4][2];
            #pragma unroll
            for (int mi = 0; mi < 4; mi++) {
                int r = wm + mi * 16 + g;
                afr[mi][0] = as[r * ASTR + k0 + tg];
                afr[mi][1] = as[(r + 8) * ASTR + k0 + tg];
                afr[mi][2] = as[r * ASTR + k0 + tg + 4];
                afr[mi][3] = as[(r + 8) * ASTR + k0 + tg + 4];
            }
            #pragma unroll
            for (int ni = 0; ni < 4; ni++) {
                int n = wn + ni * 8 + g;
                bfr[ni][0] = bs[n * ASTR + k0 + tg];
                bfr[ni][1] = bs[n * ASTR + k0 + tg + 4];
            }
            #pragma unroll
            for (int mi = 0; mi < 4; mi++)
                #pragma unroll
                for (int ni = 0; ni < 4; ni++)
                    mma_tf32(acc[mi][ni], afr[mi], bfr[ni], acc[mi][ni]);
        }
        __syncthreads();
        buf ^= 1;
    }

    #pragma unroll
    for (int mi = 0; mi < 4; mi++) {
        int row0 = rowStart + wm + mi * 16 + g;
        #pragma unroll
        for (int ni = 0; ni < 4; ni++) {
            int col = colStart + wn + ni * 8 + tg * 2;
            float2 v0, v1;
            v0.x = acc[mi][ni][0] * alpha; v0.y = acc[mi][ni][1] * alpha;
            v1.x = acc[mi][ni][2] * alpha; v1.y = acc[mi][ni][3] * alpha;
            *reinterpret_cast<float2*>(&C[(long long)row0 * N + col]) = v0;
            *reinterpret_cast<float2*>(&C[(long long)(row0 + 8) * N + col]) = v1;
        }
    }
}

// ---------------- Softmax over rows (causal: len=i+1, zero-fill tail) ----------------
__global__ void softmax_rows(float* __restrict__ P, int S, int causal)
{
    long long z = blockIdx.y;
    int i = blockIdx.x;
    float* row = P + (z * S + i) * (long long)S;
    int len = causal ? (i + 1) : S;

    float m = -INFINITY;
    for (int j = threadIdx.x; j < len; j += blockDim.x) m = fmaxf(m, row[j]);
    m = blockMax(m);

    float sum = 0.f;
    for (int j = threadIdx.x; j < len; j += blockDim.x) {
        float e = expf(row[j] - m);
        row[j] = e;
        sum += e;
    }
    sum = blockSum(sum);
    float inv = 1.f / sum;
    for (int j = threadIdx.x; j < len; j += blockDim.x) row[j] *= inv;
    for (int j = len + threadIdx.x; j < S; j += blockDim.x) row[j] = 0.f;
}

// ---------------- Fused residual-add + LayerNorm (E=768, 256 threads) ----------------
__global__ void add_ln(const float* __restrict__ X, const float* __restrict__ Hh,
                       const float* __restrict__ g, const float* __restrict__ b,
                       float* __restrict__ Y)
{
    long long row = blockIdx.x;
    const float* x = X + row * EE;
    const float* h = Hh + row * EE;
    float* y = Y + row * EE;
    int tid = threadIdx.x;

    float v[3];
    float s = 0.f;
    #pragma unroll
    for (int k = 0; k < 3; k++) {
        int c = tid + k * 256;
        v[k] = x[c] + h[c];
        s += v[k];
    }
    s = blockSum(s);
    float mean = s * (1.0f / EE);

    float q = 0.f;
    #pragma unroll
    for (int k = 0; k < 3; k++) { float d = v[k] - mean; q += d * d; }
    q = blockSum(q);
    float inv = rsqrtf(q * (1.0f / EE) + LN_EPS);

    #pragma unroll
    for (int k = 0; k < 3; k++) {
        int c = tid + k * 256;
        y[c] = (v[k] - mean) * inv * g[c] + b[c];
    }
}

// ---------------- Orchestration ----------------
extern "C" void kernel_launch(void* const* d_in, const int* in_sizes, int n_in,
                              void* d_out, int out_size)
{
    const float* x     = (const float*)d_in[0];
    const float* kv    = (const float*)d_in[1];
    const float* wq_w  = (const float*)d_in[2];
    const float* wq_b  = (const float*)d_in[3];
    const float* wk_w  = (const float*)d_in[4];
    const float* wk_b  = (const float*)d_in[5];
    const float* wv_w  = (const float*)d_in[6];
    const float* wv_b  = (const float*)d_in[7];
    const float* ln1_g = (const float*)d_in[8];
    const float* ln1_b = (const float*)d_in[9];
    const float* wq2_w = (const float*)d_in[10];
    const float* wq2_b = (const float*)d_in[11];
    const float* wk2_w = (const float*)d_in[12];
    const float* wk2_b = (const float*)d_in[13];
    const float* wv2_w = (const float*)d_in[14];
    const float* wv2_b = (const float*)d_in[15];
    const float* ln2_g = (const float*)d_in[16];
    const float* ln2_b = (const float*)d_in[17];
    const float* mlp_w1= (const float*)d_in[18];
    const float* mlp_b1= (const float*)d_in[19];
    const float* mlp_w2= (const float*)d_in[20];
    const float* mlp_b2= (const float*)d_in[21];
    const float* ln3_g = (const float*)d_in[22];
    const float* ln3_b = (const float*)d_in[23];
    float* out = (float*)d_out;

    float *q, *k, *v, *t, *x1, *x2, *sc, *hh;
    cudaGetSymbolAddress((void**)&q,  g_q);
    cudaGetSymbolAddress((void**)&k,  g_k);
    cudaGetSymbolAddress((void**)&v,  g_v);
    cudaGetSymbolAddress((void**)&t,  g_t);
    cudaGetSymbolAddress((void**)&x1, g_x1);
    cudaGetSymbolAddress((void**)&x2, g_x2);
    cudaGetSymbolAddress((void**)&sc, g_scores);
    cudaGetSymbolAddress((void**)&hh, g_h);

    const float scale = 1.0f / sqrtf((float)EE);
    dim3 blk(256);
    dim3 gProj(EE / 128, MM / 128, 1);       // (6,128)
    dim3 gMlp1(HH / 128, MM / 128, 1);       // (24,128)
    dim3 gScore(SS / 128, SS / 128, BB);     // (16,16,8)
    dim3 gPV(EE / 128, SS / 128, BB);        // (6,16,8)
    dim3 gSm(SS, BB);
    dim3 gLn(MM);

    // --- causal self-attention ---
    mma_nn<<<gProj, blk>>>(x, wq_w, wq_b, q, MM, EE, EE, 0, 0, 0, 0, 0);
    mma_nn<<<gProj, blk>>>(x, wk_w, wk_b, k, MM, EE, EE, 0, 0, 0, 0, 0);
    mma_nn<<<gProj, blk>>>(x, wv_w, wv_b, v, MM, EE, EE, 0, 0, 0, 0, 0);
    mma_nt<<<gScore, blk>>>(q, k, sc, SS, SS, EE,
                            (long long)SS * EE, (long long)SS * EE,
                            (long long)SS * SS, scale, 1);
    softmax_rows<<<gSm, blk>>>(sc, SS, 1);
    mma_nn<<<gPV, blk>>>(sc, v, nullptr, t, SS, EE, SS,
                         (long long)SS * SS, (long long)SS * EE,
                         (long long)SS * EE, 0, 1);
    add_ln<<<gLn, blk>>>(x, t, ln1_g, ln1_b, x1);

    // --- cross-attention ---
    mma_nn<<<gProj, blk>>>(x1, wq2_w, wq2_b, q, MM, EE, EE, 0, 0, 0, 0, 0);
    mma_nn<<<gProj, blk>>>(kv, wk2_w, wk2_b, k, MM, EE, EE, 0, 0, 0, 0, 0);
    mma_nn<<<gProj, blk>>>(kv, wv2_w, wv2_b, v, MM, EE, EE, 0, 0, 0, 0, 0);
    mma_nt<<<gScore, blk>>>(q, k, sc, SS, SS, EE,
                            (long long)SS * EE, (long long)SS * EE,
                            (long long)SS * SS, scale, 0);
    softmax_rows<<<gSm, blk>>>(sc, SS, 0);
    mma_nn<<<gPV, blk>>>(sc, v, nullptr, t, SS, EE, SS,
                         (long long)SS * SS, (long long)SS * EE,
                         (long long)SS * EE, 0, 0);
    add_ln<<<gLn, blk>>>(x1, t, ln2_g, ln2_b, x2);

    // --- MLP (ReLU after both linears) ---
    mma_nn<<<gMlp1, blk>>>(x2, mlp_w1, mlp_b1, hh, MM, HH, EE, 0, 0, 0, 1, 0);
    mma_nn<<<gProj, blk>>>(hh, mlp_w2, mlp_b2, t, MM, EE, HH, 0, 0, 0, 1, 0);
    add_ln<<<gLn, blk>>>(x2, t, ln3_g, ln3_b, out);
}

// round 6
// speedup vs baseline: 3.8110x; 1.2245x over previous
#include <cuda_runtime.h>
#include <math.h>
#include <stdint.h>

// ---------------- Problem constants ----------------
#define BB 8
#define SS 2048
#define EE 768
#define HH 3072          // R*E
#define MM (BB*SS)       // 16384
#define LN_EPS 1e-5f

// ---------------- Scratch (device globals; no allocs allowed) ----------------
__device__ float g_q[MM*EE];
__device__ float g_k[MM*EE];
__device__ float g_v[MM*EE];
__device__ float g_t[MM*EE];
__device__ float g_x1[MM*EE];
__device__ float g_x2[MM*EE];
__device__ float g_scores[(long long)BB*SS*SS];
__device__ float g_h[(long long)MM*HH];

// ---------------- Reductions ----------------
__device__ __forceinline__ float warpSum(float v) {
    #pragma unroll
    for (int o = 16; o > 0; o >>= 1) v += __shfl_xor_sync(0xffffffffu, v, o);
    return v;
}
__device__ __forceinline__ float warpMax(float v) {
    #pragma unroll
    for (int o = 16; o > 0; o >>= 1) v = fmaxf(v, __shfl_xor_sync(0xffffffffu, v, o));
    return v;
}
__device__ float blockSum(float v) {
    __shared__ float sh[32];
    int lane = threadIdx.x & 31, w = threadIdx.x >> 5;
    v = warpSum(v);
    if (lane == 0) sh[w] = v;
    __syncthreads();
    int nw = (blockDim.x + 31) >> 5;
    float r = (threadIdx.x < nw) ? sh[threadIdx.x] : 0.f;
    if (w == 0) r = warpSum(r);
    if (threadIdx.x == 0) sh[0] = r;
    __syncthreads();
    r = sh[0];
    __syncthreads();
    return r;
}
__device__ float blockMax(float v) {
    __shared__ float sh[32];
    int lane = threadIdx.x & 31, w = threadIdx.x >> 5;
    v = warpMax(v);
    if (lane == 0) sh[w] = v;
    __syncthreads();
    int nw = (blockDim.x + 31) >> 5;
    float r = (threadIdx.x < nw) ? sh[threadIdx.x] : -INFINITY;
    if (w == 0) r = warpMax(r);
    if (threadIdx.x == 0) sh[0] = r;
    __syncthreads();
    r = sh[0];
    __syncthreads();
    return r;
}

// ---------------- MMA / cp.async / ldmatrix helpers ----------------
// tf32 mma reads only the top 19 bits of each operand register, so raw fp32
// bits are a valid (RZ-truncated) tf32 operand. No cvt needed.
__device__ __forceinline__ void mma_tf32(float* d, const uint32_t* a,
                                         const uint32_t* b, const float* c) {
    asm volatile(
        "mma.sync.aligned.m16n8k8.row.col.f32.tf32.tf32.f32 "
        "{%0,%1,%2,%3}, {%4,%5,%6,%7}, {%8,%9}, {%10,%11,%12,%13};\n"
        : "=f"(d[0]), "=f"(d[1]), "=f"(d[2]), "=f"(d[3])
        : "r"(a[0]), "r"(a[1]), "r"(a[2]), "r"(a[3]),
          "r"(b[0]), "r"(b[1]),
          "f"(c[0]), "f"(c[1]), "f"(c[2]), "f"(c[3]));
}
__device__ __forceinline__ void cp16(uint32_t dst, const void* src) {
    asm volatile("cp.async.cg.shared.global [%0], [%1], 16;\n" :: "r"(dst), "l"(src));
}
__device__ __forceinline__ void cp_commit() {
    asm volatile("cp.async.commit_group;\n");
}
__device__ __forceinline__ void cp_wait0() {
    asm volatile("cp.async.wait_group 0;\n");
}
__device__ __forceinline__ void cp_wait1() {
    asm volatile("cp.async.wait_group 1;\n");
}
// ldmatrix on tf32 data: each 8x8 b16 tile == 8x4 b32 tile; register layout
// matches the tf32 mma fragment (lane -> (row=lane/4, col=lane%4)).
__device__ __forceinline__ void ldsm4(uint32_t* r, uint32_t addr) {
    asm volatile("ldmatrix.sync.aligned.m8n8.x4.shared.b16 {%0,%1,%2,%3}, [%4];\n"
        : "=r"(r[0]), "=r"(r[1]), "=r"(r[2]), "=r"(r[3]) : "r"(addr));
}
__device__ __forceinline__ void ldsm2(uint32_t* r, uint32_t addr) {
    asm volatile("ldmatrix.sync.aligned.m8n8.x2.shared.b16 {%0,%1}, [%2];\n"
        : "=r"(r[0]), "=r"(r[1]) : "r"(addr));
}

// ---------------- TF32 GEMM: CTA 128x128, BK=32, 256 thr, 8 warps of 64x32 ----------------
// A smem: m-major, stride 36 (ldmatrix phases hit all 32 banks: (4m+k0)%32).
// B smem (NN): k-major, stride 136 (LDS banks (8tg+g)%32 distinct).
// 2-stage cp.async double buffer in dynamic smem.
#define BK3 32
#define ASTR2 36
#define BSTR 136
#define A_EL (128*ASTR2)   // 4608 u32 per stage
#define B_EL (BK3*BSTR)    // 4352 u32 per stage
#define SMEM_NN ((2*(A_EL+B_EL))*4)   // 71680 B
#define SMEM_NT ((4*A_EL)*4)          // 73728 B

// ---- shared NN mainloop body (A row-major [*,K], B k-major [K,N]) ----
__device__ __forceinline__ void gemm_nn_body(
    const float* __restrict__ A, const float* __restrict__ B,
    const float* __restrict__ bias, float* __restrict__ C,
    int N, int K, int rowStart, int colStart, int Keff, int relu)
{
    extern __shared__ uint32_t dynsmem[];
    uint32_t asBase = (uint32_t)__cvta_generic_to_shared(dynsmem);
    uint32_t bsBase = asBase + 2 * A_EL * 4;

    int tid = threadIdx.x, lane = tid & 31, wid = tid >> 5;
    int wm = (wid >> 2) * 64, wn = (wid & 3) * 32;
    int g = lane >> 2, tg = lane & 3;
    int ntiles = Keff / BK3;

    int am[4], ak[4], bk[4], bn[4];
    #pragma unroll
    for (int i = 0; i < 4; i++) {
        int f = tid + i * 256;
        am[i] = f >> 3;  ak[i] = (f & 7) * 4;
        bk[i] = f >> 5;  bn[i] = (f & 31) * 4;
    }

    auto loadTile = [&](int kt, int s) {
        #pragma unroll
        for (int i = 0; i < 4; i++)
            cp16(asBase + (s * A_EL + am[i] * ASTR2 + ak[i]) * 4,
                 &A[(long long)(rowStart + am[i]) * K + kt + ak[i]]);
        #pragma unroll
        for (int i = 0; i < 4; i++)
            cp16(bsBase + (s * B_EL + bk[i] * BSTR + bn[i]) * 4,
                 &B[(long long)(kt + bk[i]) * N + colStart + bn[i]]);
        cp_commit();
    };

    // ldmatrix lane offset: lanes 0-15 -> m rows (lane&15), lanes 16-31 -> k+4 half
    uint32_t aLaneOff = ((wm + (lane & 15)) * ASTR2 + (lane >> 4) * 4) * 4;

    float acc[4][4][4] = {};
    loadTile(0, 0);
    int buf = 0;
    for (int it = 0; it < ntiles; it++) {
        if (it + 1 < ntiles) { loadTile((it + 1) * BK3, buf ^ 1); cp_wait1(); }
        else cp_wait0();
        __syncthreads();

        uint32_t aS = asBase + buf * A_EL * 4 + aLaneOff;
        const uint32_t* bs = dynsmem + 2 * A_EL + buf * B_EL;
        #pragma unroll
        for (int ks = 0; ks < 4; ks++) {
            int k0 = ks * 8;
            uint32_t afr[4][4], bfr[4][2];
            #pragma unroll
            for (int mi = 0; mi < 4; mi++)
                ldsm4(afr[mi], aS + (mi * 16 * ASTR2 + k0) * 4);
            #pragma unroll
            for (int ni = 0; ni < 4; ni++) {
                int n = wn + ni * 8 + g;
                bfr[ni][0] = bs[(k0 + tg) * BSTR + n];
                bfr[ni][1] = bs[(k0 + tg + 4) * BSTR + n];
            }
            #pragma unroll
            for (int mi = 0; mi < 4; mi++)
                #pragma unroll
                for (int ni = 0; ni < 4; ni++)
                    mma_tf32(acc[mi][ni], afr[mi], bfr[ni], acc[mi][ni]);
        }
        __syncthreads();
        buf ^= 1;
    }

    #pragma unroll
    for (int mi = 0; mi < 4; mi++) {
        int row0 = rowStart + wm + mi * 16 + g;
        #pragma unroll
        for (int ni = 0; ni < 4; ni++) {
            int col = colStart + wn + ni * 8 + tg * 2;
            float2 v0, v1;
            v0.x = acc[mi][ni][0]; v0.y = acc[mi][ni][1];
            v1.x = acc[mi][ni][2]; v1.y = acc[mi][ni][3];
            if (bias) {
                float b0 = bias[col], b1 = bias[col + 1];
                v0.x += b0; v0.y += b1; v1.x += b0; v1.y += b1;
            }
            if (relu) {
                v0.x = fmaxf(v0.x, 0.f); v0.y = fmaxf(v0.y, 0.f);
                v1.x = fmaxf(v1.x, 0.f); v1.y = fmaxf(v1.y, 0.f);
            }
            *reinterpret_cast<float2*>(&C[(long long)row0 * N + col]) = v0;
            *reinterpret_cast<float2*>(&C[(long long)(row0 + 8) * N + col]) = v1;
        }
    }
}

// ---- NN: batched via z strides; causalKlim limits K to rowStart+128.
__global__ __launch_bounds__(256, 2)
void mma_nn(const float* __restrict__ A, const float* __restrict__ B,
            const float* __restrict__ bias, float* __restrict__ C,
            int N, int K, long long sA, long long sB, long long sC,
            int relu, int causalKlim)
{
    int z = blockIdx.z;
    A += (long long)z * sA;  B += (long long)z * sB;  C += (long long)z * sC;
    int rowStart = blockIdx.y * 128, colStart = blockIdx.x * 128;
    int Keff = K;
    if (causalKlim) { int kl = rowStart + 128; if (kl < Keff) Keff = kl; }
    gemm_nn_body(A, B, bias, C, N, K, rowStart, colStart, Keff, relu);
}

// ---- fused triple projection: z selects (A, W, bias, C) tuple.
__global__ __launch_bounds__(256, 2)
void mma_nn3(const float* __restrict__ A0, const float* __restrict__ A1,
             const float* __restrict__ A2,
             const float* __restrict__ W0, const float* __restrict__ W1,
             const float* __restrict__ W2,
             const float* __restrict__ b0, const float* __restrict__ b1,
             const float* __restrict__ b2,
             float* __restrict__ C0, float* __restrict__ C1,
             float* __restrict__ C2, int N, int K)
{
    int z = blockIdx.z;
    const float* A = (z == 0) ? A0 : (z == 1 ? A1 : A2);
    const float* W = (z == 0) ? W0 : (z == 1 ? W1 : W2);
    const float* bi = (z == 0) ? b0 : (z == 1 ? b1 : b2);
    float* C = (z == 0) ? C0 : (z == 1 ? C1 : C2);
    gemm_nn_body(A, W, bi, C, N, K, blockIdx.y * 128, blockIdx.x * 128, K, 0);
}

// ---- NT (scores): C = alpha * A[M,K] @ B[N,K]^T. Both operands m-major smem,
// A frags via ldmatrix.x4, B frags via ldmatrix.x2. Causal skips masked blocks.
__global__ __launch_bounds__(256, 2)
void mma_nt(const float* __restrict__ A, const float* __restrict__ B,
            float* __restrict__ C, int N, int K,
            long long sA, long long sB, long long sC,
            float alpha, int causal)
{
    int rowStart = blockIdx.y * 128;
    int colStart = blockIdx.x * 128;
    if (causal && (rowStart + 128 - 1) < colStart) return;  // fully masked

    extern __shared__ uint32_t dynsmem[];
    uint32_t asBase = (uint32_t)__cvta_generic_to_shared(dynsmem);
    uint32_t bsBase = asBase + 2 * A_EL * 4;

    int z = blockIdx.z;
    A += (long long)z * sA;  B += (long long)z * sB;  C += (long long)z * sC;
    int ntiles = K / BK3;

    int tid = threadIdx.x, lane = tid & 31, wid = tid >> 5;
    int wm = (wid >> 2) * 64, wn = (wid & 3) * 32;
    int g = lane >> 2, tg = lane & 3;

    int am[4], ak[4];
    #pragma unroll
    for (int i = 0; i < 4; i++) {
        int f = tid + i * 256;
        am[i] = f >> 3;  ak[i] = (f & 7) * 4;
    }

    auto loadTile = [&](int kt, int s) {
        #pragma unroll
        for (int i = 0; i < 4; i++)
            cp16(asBase + (s * A_EL + am[i] * ASTR2 + ak[i]) * 4,
                 &A[(long long)(rowStart + am[i]) * K + kt + ak[i]]);
        #pragma unroll
        for (int i = 0; i < 4; i++)
            cp16(bsBase + (s * A_EL + am[i] * ASTR2 + ak[i]) * 4,
                 &B[(long long)(colStart + am[i]) * K + kt + ak[i]]);
        cp_commit();
    };

    uint32_t aLaneOff = ((wm + (lane & 15)) * ASTR2 + (lane >> 4) * 4) * 4;
    uint32_t bLaneOff = ((wn + (lane & 7)) * ASTR2 + ((lane >> 3) & 1) * 4) * 4;

    float acc[4][4][4] = {};
    loadTile(0, 0);
    int buf = 0;
    for (int it = 0; it < ntiles; it++) {
        if (it + 1 < ntiles) { loadTile((it + 1) * BK3, buf ^ 1); cp_wait1(); }
        else cp_wait0();
        __syncthreads();

        uint32_t aS = asBase + buf * A_EL * 4 + aLaneOff;
        uint32_t bS = bsBase + buf * A_EL * 4 + bLaneOff;
        #pragma unroll
        for (int ks = 0; ks < 4; ks++) {
            int k0 = ks * 8;
            uint32_t afr[4][4], bfr[4][2];
            #pragma unroll
            for (int mi = 0; mi < 4; mi++)
                ldsm4(afr[mi], aS + (mi * 16 * ASTR2 + k0) * 4);
            #pragma unroll
            for (int ni = 0; ni < 4; ni++)
                ldsm2(bfr[ni], bS + (ni * 8 * ASTR2 + k0) * 4);
            #pragma unroll
            for (int mi = 0; mi < 4; mi++)
                #pragma unroll
                for (int ni = 0; ni < 4; ni++)
                    mma_tf32(acc[mi][ni], afr[mi], bfr[ni], acc[mi][ni]);
        }
        __syncthreads();
        buf ^= 1;
    }

    #pragma unroll
    for (int mi = 0; mi < 4; mi++) {
        int row0 = rowStart + wm + mi * 16 + g;
        #pragma unroll
        for (int ni = 0; ni < 4; ni++) {
            int col = colStart + wn + ni * 8 + tg * 2;
            float2 v0, v1;
            v0.x = acc[mi][ni][0] * alpha; v0.y = acc[mi][ni][1] * alpha;
            v1.x = acc[mi][ni][2] * alpha; v1.y = acc[mi][ni][3] * alpha;
            *reinterpret_cast<float2*>(&C[(long long)row0 * N + col]) = v0;
            *reinterpret_cast<float2*>(&C[(long long)(row0 + 8) * N + col]) = v1;
        }
    }
}

// ---------------- Single-pass register softmax (S=2048, 256 thr, 8 vals/thr) ----
// Causal: mask j>=len to -inf (exp->0), store only up to the padded diagonal
// block (PV reads k < (i/128+1)*128 only).
__global__ void softmax_rows(float* __restrict__ P, int S, int causal)
{
    long long z = blockIdx.y;
    int i = blockIdx.x;
    float* row = P + (z * S + i) * (long long)S;
    int len = causal ? (i + 1) : S;
    int lenPad = causal ? (((i >> 7) + 1) << 7) : S;

    int c0 = threadIdx.x * 4, c1 = c0 + 1024;
    float4 u0 = *reinterpret_cast<const float4*>(&row[c0]);
    float4 u1 = *reinterpret_cast<const float4*>(&row[c1]);
    float va[8] = {u0.x, u0.y, u0.z, u0.w, u1.x, u1.y, u1.z, u1.w};

    float mx = -INFINITY;
    #pragma unroll
    for (int e = 0; e < 4; e++) {
        if (c0 + e >= len) va[e] = -INFINITY;
        mx = fmaxf(mx, va[e]);
    }
    #pragma unroll
    for (int e = 0; e < 4; e++) {
        if (c1 + e >= len) va[4 + e] = -INFINITY;
        mx = fmaxf(mx, va[4 + e]);
    }
    mx = blockMax(mx);

    float s = 0.f;
    #pragma unroll
    for (int e = 0; e < 8; e++) { va[e] = expf(va[e] - mx); s += va[e]; }
    s = blockSum(s);
    float inv = 1.f / s;
    #pragma unroll
    for (int e = 0; e < 8; e++) va[e] *= inv;

    if (c0 < lenPad) {
        float4 w = {va[0], va[1], va[2], va[3]};
        *reinterpret_cast<float4*>(&row[c0]) = w;
    }
    if (c1 < lenPad) {
        float4 w = {va[4], va[5], va[6], va[7]};
        *reinterpret_cast<float4*>(&row[c1]) = w;
    }
}

// ---------------- Fused residual-add + LayerNorm (E=768, 256 threads) ----------------
__global__ void add_ln(const float* __restrict__ X, const float* __restrict__ Hh,
                       const float* __restrict__ g, const float* __restrict__ b,
                       float* __restrict__ Y)
{
    long long row = blockIdx.x;
    const float* x = X + row * EE;
    const float* h = Hh + row * EE;
    float* y = Y + row * EE;
    int tid = threadIdx.x;

    float v[3];
    float s = 0.f;
    #pragma unroll
    for (int k = 0; k < 3; k++) {
        int c = tid + k * 256;
        v[k] = x[c] + h[c];
        s += v[k];
    }
    s = blockSum(s);
    float mean = s * (1.0f / EE);

    float q = 0.f;
    #pragma unroll
    for (int k = 0; k < 3; k++) { float d = v[k] - mean; q += d * d; }
    q = blockSum(q);
    float inv = rsqrtf(q * (1.0f / EE) + LN_EPS);

    #pragma unroll
    for (int k = 0; k < 3; k++) {
        int c = tid + k * 256;
        y[c] = (v[k] - mean) * inv * g[c] + b[c];
    }
}

// ---------------- Orchestration ----------------
extern "C" void kernel_launch(void* const* d_in, const int* in_sizes, int n_in,
                              void* d_out, int out_size)
{
    const float* x     = (const float*)d_in[0];
    const float* kv    = (const float*)d_in[1];
    const float* wq_w  = (const float*)d_in[2];
    const float* wq_b  = (const float*)d_in[3];
    const float* wk_w  = (const float*)d_in[4];
    const float* wk_b  = (const float*)d_in[5];
    const float* wv_w  = (const float*)d_in[6];
    const float* wv_b  = (const float*)d_in[7];
    const float* ln1_g = (const float*)d_in[8];
    const float* ln1_b = (const float*)d_in[9];
    const float* wq2_w = (const float*)d_in[10];
    const float* wq2_b = (const float*)d_in[11];
    const float* wk2_w = (const float*)d_in[12];
    const float* wk2_b = (const float*)d_in[13];
    const float* wv2_w = (const float*)d_in[14];
    const float* wv2_b = (const float*)d_in[15];
    const float* ln2_g = (const float*)d_in[16];
    const float* ln2_b = (const float*)d_in[17];
    const float* mlp_w1= (const float*)d_in[18];
    const float* mlp_b1= (const float*)d_in[19];
    const float* mlp_w2= (const float*)d_in[20];
    const float* mlp_b2= (const float*)d_in[21];
    const float* ln3_g = (const float*)d_in[22];
    const float* ln3_b = (const float*)d_in[23];
    float* out = (float*)d_out;

    float *q, *k, *v, *t, *x1, *x2, *sc, *hh;
    cudaGetSymbolAddress((void**)&q,  g_q);
    cudaGetSymbolAddress((void**)&k,  g_k);
    cudaGetSymbolAddress((void**)&v,  g_v);
    cudaGetSymbolAddress((void**)&t,  g_t);
    cudaGetSymbolAddress((void**)&x1, g_x1);
    cudaGetSymbolAddress((void**)&x2, g_x2);
    cudaGetSymbolAddress((void**)&sc, g_scores);
    cudaGetSymbolAddress((void**)&hh, g_h);

    cudaFuncSetAttribute(mma_nn,  cudaFuncAttributeMaxDynamicSharedMemorySize, SMEM_NN);
    cudaFuncSetAttribute(mma_nn3, cudaFuncAttributeMaxDynamicSharedMemorySize, SMEM_NN);
    cudaFuncSetAttribute(mma_nt,  cudaFuncAttributeMaxDynamicSharedMemorySize, SMEM_NT);

    const float scale = 1.0f / sqrtf((float)EE);
    dim3 blk(256);
    dim3 gProj(EE / 128, MM / 128, 1);        // (6,128)
    dim3 gProj3(EE / 128, MM / 128, 3);       // (6,128,3)
    dim3 gMlp1(HH / 128, MM / 128, 1);        // (24,128)
    dim3 gScore(SS / 128, SS / 128, BB);      // (16,16,8)
    dim3 gPV(EE / 128, SS / 128, BB);         // (6,16,8)
    dim3 gSm(SS, BB);
    dim3 gLn(MM);

    // --- causal self-attention ---
    mma_nn3<<<gProj3, blk, SMEM_NN>>>(x, x, x, wq_w, wk_w, wv_w,
                                      wq_b, wk_b, wv_b, q, k, v, EE, EE);
    mma_nt<<<gScore, blk, SMEM_NT>>>(q, k, sc, SS, EE,
                                     (long long)SS * EE, (long long)SS * EE,
                                     (long long)SS * SS, scale, 1);
    softmax_rows<<<gSm, blk>>>(sc, SS, 1);
    mma_nn<<<gPV, blk, SMEM_NN>>>(sc, v, nullptr, t, EE, SS,
                                  (long long)SS * SS, (long long)SS * EE,
                                  (long long)SS * EE, 0, 1);
    add_ln<<<gLn, blk>>>(x, t, ln1_g, ln1_b, x1);

    // --- cross-attention ---
    mma_nn3<<<gProj3, blk, SMEM_NN>>>(x1, kv, kv, wq2_w, wk2_w, wv2_w,
                                      wq2_b, wk2_b, wv2_b, q, k, v, EE, EE);
    mma_nt<<<gScore, blk, SMEM_NT>>>(q, k, sc, SS, EE,
                                     (long long)SS * EE, (long long)SS * EE,
                                     (long long)SS * SS, scale, 0);
    softmax_rows<<<gSm, blk>>>(sc, SS, 0);
    mma_nn<<<gPV, blk, SMEM_NN>>>(sc, v, nullptr, t, EE, SS,
                                  (long long)SS * SS, (long long)SS * EE,
                                  (long long)SS * EE, 0, 0);
    add_ln<<<gLn, blk>>>(x1, t, ln2_g, ln2_b, x2);

    // --- MLP (ReLU after both linears) ---
    mma_nn<<<gMlp1, blk, SMEM_NN>>>(x2, mlp_w1, mlp_b1, hh, HH, EE, 0, 0, 0, 1, 0);
    mma_nn<<<gProj, blk, SMEM_NN>>>(hh, mlp_w2, mlp_b2, t, EE, HH, 0, 0, 0, 1, 0);
    add_ln<<<gLn, blk>>>(x2, t, ln3_g, ln3_b, out);
}

// round 8
// speedup vs baseline: 7.5905x; 1.9917x over previous
#include <cuda_runtime.h>
#include <cuda_fp16.h>
#include <math.h>
#include <stdint.h>

// ---------------- Problem constants ----------------
#define BB 8
#define SS 2048
#define EE 768
#define HH 3072          // R*E
#define MM (BB*SS)       // 16384
#define LN_EPS 1e-5f

// fp16 GEMM tiling: CTA 128x128, BK=64, 256 thr, 8 warps of 64x32
#define HBK 64
#define STAGE_BYTES 32768            // A 16KB + B 16KB per stage
#define DSM (2*STAGE_BYTES)          // 64KB dynamic smem

// ---------------- Scratch (device globals; no allocs allowed) ----------------
__device__ __half g_qkv16[5LL*MM*EE];   // 0=q/q2, 1=k, 2=v, 3=k2, 4=v2
__device__ __half g_x16[MM*EE];
__device__ __half g_kv16[MM*EE];
__device__ __half g_x1h[MM*EE];
__device__ __half g_x2h[MM*EE];
__device__ __half g_hh16[(long long)MM*HH];
__device__ __half g_p16[(long long)BB*SS*SS];
__device__ __half g_wt16[6*EE*EE + 2*EE*HH];  // wqT,wkT,wvT,wk2T,wv2T,wq2T,w1T,w2T
__device__ float  g_sc[(long long)BB*SS*SS];
__device__ float  g_t[MM*EE];
__device__ float  g_x1[MM*EE];
__device__ float  g_x2[MM*EE];

// ---------------- Reductions ----------------
__device__ __forceinline__ float warpSum(float v) {
    #pragma unroll
    for (int o = 16; o > 0; o >>= 1) v += __shfl_xor_sync(0xffffffffu, v, o);
    return v;
}
__device__ __forceinline__ float warpMax(float v) {
    #pragma unroll
    for (int o = 16; o > 0; o >>= 1) v = fmaxf(v, __shfl_xor_sync(0xffffffffu, v, o));
    return v;
}
__device__ float blockSum(float v) {
    __shared__ float sh[32];
    int lane = threadIdx.x & 31, w = threadIdx.x >> 5;
    v = warpSum(v);
    if (lane == 0) sh[w] = v;
    __syncthreads();
    int nw = (blockDim.x + 31) >> 5;
    float r = (threadIdx.x < nw) ? sh[threadIdx.x] : 0.f;
    if (w == 0) r = warpSum(r);
    if (threadIdx.x == 0) sh[0] = r;
    __syncthreads();
    r = sh[0];
    __syncthreads();
    return r;
}
__device__ float blockMax(float v) {
    __shared__ float sh[32];
    int lane = threadIdx.x & 31, w = threadIdx.x >> 5;
    v = warpMax(v);
    if (lane == 0) sh[w] = v;
    __syncthreads();
    int nw = (blockDim.x + 31) >> 5;
    float r = (threadIdx.x < nw) ? sh[threadIdx.x] : -INFINITY;
    if (w == 0) r = warpMax(r);
    if (threadIdx.x == 0) sh[0] = r;
    __syncthreads();
    r = sh[0];
    __syncthreads();
    return r;
}

// ---------------- PTX helpers ----------------
__device__ __forceinline__ void cp16(uint32_t dst, const void* src) {
    asm volatile("cp.async.cg.shared.global [%0], [%1], 16;\n" :: "r"(dst), "l"(src));
}
__device__ __forceinline__ void cp_commit() { asm volatile("cp.async.commit_group;\n"); }
__device__ __forceinline__ void cp_wait0()  { asm volatile("cp.async.wait_group 0;\n"); }
__device__ __forceinline__ void cp_wait1()  { asm volatile("cp.async.wait_group 1;\n"); }

__device__ __forceinline__ void mma_f16(float* d, const uint32_t* a,
                                        const uint32_t* b, const float* c) {
    asm volatile(
        "mma.sync.aligned.m16n8k16.row.col.f32.f16.f16.f32 "
        "{%0,%1,%2,%3}, {%4,%5,%6,%7}, {%8,%9}, {%10,%11,%12,%13};\n"
        : "=f"(d[0]), "=f"(d[1]), "=f"(d[2]), "=f"(d[3])
        : "r"(a[0]), "r"(a[1]), "r"(a[2]), "r"(a[3]),
          "r"(b[0]), "r"(b[1]),
          "f"(c[0]), "f"(c[1]), "f"(c[2]), "f"(c[3]));
}
__device__ __forceinline__ void ldsm4(uint32_t* r, uint32_t addr) {
    asm volatile("ldmatrix.sync.aligned.m8n8.x4.shared.b16 {%0,%1,%2,%3}, [%4];\n"
        : "=r"(r[0]), "=r"(r[1]), "=r"(r[2]), "=r"(r[3]) : "r"(addr));
}
__device__ __forceinline__ void ldsm4t(uint32_t* r, uint32_t addr) {
    asm volatile("ldmatrix.sync.aligned.m8n8.x4.trans.shared.b16 {%0,%1,%2,%3}, [%4];\n"
        : "=r"(r[0]), "=r"(r[1]), "=r"(r[2]), "=r"(r[3]) : "r"(addr));
}

// ---------------- fp16 GEMM body ----------------
// NT (BTRANS=0): C[M,N] = A[M,K] @ B[N,K]^T ; btrans (BTRANS=1): B stored [K,N].
// A smem: 128 rows x 64 halves (128B), 16B chunk c of row m at (c ^ (m&7)).
// B NT smem: same geometry (rows = n). B trans smem: 64 k-rows x 128 halves
// (256B), chunk nc of row k at (nc ^ (k&7)).
template<int BTRANS, int CHALF>
__device__ void hg_body(const __half* __restrict__ A, const __half* __restrict__ B,
                        const float* __restrict__ bias, void* __restrict__ Cv,
                        int N, int K, int rowStart, int colStart, int Keff,
                        float alpha, int relu)
{
    extern __shared__ char dynsm[];
    uint32_t smBase = (uint32_t)__cvta_generic_to_shared(dynsm);

    int tid = threadIdx.x, lane = tid & 31, wid = tid >> 5;
    int wm = (wid >> 2) * 64, wn = (wid & 3) * 32;
    int g = lane >> 2, tg = lane & 3;
    int T = Keff / HBK;

    auto loadTile = [&](int kt, int s) {
        uint32_t aB = smBase + s * STAGE_BYTES;
        uint32_t bB = aB + 16384;
        #pragma unroll
        for (int i = 0; i < 4; i++) {
            int idx = tid + i * 256;             // 1024 chunks
            int m = idx >> 3, c = idx & 7;
            cp16(aB + m * 128 + ((c ^ (m & 7)) << 4),
                 &A[(long long)(rowStart + m) * K + kt + c * 8]);
        }
        if (!BTRANS) {
            #pragma unroll
            for (int i = 0; i < 4; i++) {
                int idx = tid + i * 256;
                int n = idx >> 3, c = idx & 7;
                cp16(bB + n * 128 + ((c ^ (n & 7)) << 4),
                     &B[(long long)(colStart + n) * K + kt + c * 8]);
            }
        } else {
            #pragma unroll
            for (int i = 0; i < 4; i++) {
                int idx = tid + i * 256;
                int k = idx >> 4, nc = idx & 15;
                cp16(bB + k * 256 + ((nc ^ (k & 7)) << 4),
                     &B[(long long)(kt + k) * N + colStart + nc * 8]);
            }
        }
        cp_commit();
    };

    float acc[4][4][4] = {};
    loadTile(0, 0);
    int buf = 0;
    for (int it = 0; it < T; it++) {
        if (it + 1 < T) { loadTile((it + 1) * HBK, buf ^ 1); cp_wait1(); }
        else cp_wait0();
        __syncthreads();

        uint32_t aT = smBase + buf * STAGE_BYTES;
        uint32_t bT = aT + 16384;
        #pragma unroll
        for (int ks = 0; ks < 4; ks++) {
            uint32_t afr[4][4], bfr[4][2];
            #pragma unroll
            for (int mi = 0; mi < 4; mi++) {
                int m = wm + mi * 16 + (lane & 15);
                int c = 2 * ks + (lane >> 4);
                ldsm4(afr[mi], aT + m * 128 + ((c ^ (m & 7)) << 4));
            }
            if (!BTRANS) {
                #pragma unroll
                for (int h = 0; h < 2; h++) {
                    int n = wn + h * 16 + (lane & 7) + ((lane >> 4) & 1) * 8;
                    int c = 2 * ks + ((lane >> 3) & 1);
                    ldsm4(&bfr[2 * h][0], bT + n * 128 + ((c ^ (n & 7)) << 4));
                }
            } else {
                #pragma unroll
                for (int h = 0; h < 2; h++) {
                    int k = ks * 16 + (lane & 7) + ((lane >> 3) & 1) * 8;
                    int nc = (wn >> 3) + h * 2 + ((lane >> 4) & 1);
                    ldsm4t(&bfr[2 * h][0], bT + k * 256 + ((nc ^ (k & 7)) << 4));
                }
            }
            #pragma unroll
            for (int mi = 0; mi < 4; mi++)
                #pragma unroll
                for (int ni = 0; ni < 4; ni++)
                    mma_f16(acc[mi][ni], afr[mi], bfr[ni], acc[mi][ni]);
        }
        __syncthreads();
        buf ^= 1;
    }

    // Epilogue
    #pragma unroll
    for (int mi = 0; mi < 4; mi++) {
        int row0 = rowStart + wm + mi * 16 + g;
        #pragma unroll
        for (int ni = 0; ni < 4; ni++) {
            int col = colStart + wn + ni * 8 + tg * 2;
            float e[4];
            #pragma unroll
            for (int j = 0; j < 4; j++) e[j] = acc[mi][ni][j] * alpha;
            if (bias) {
                float b0 = bias[col], b1 = bias[col + 1];
                e[0] += b0; e[1] += b1; e[2] += b0; e[3] += b1;
            }
            if (relu) {
                #pragma unroll
                for (int j = 0; j < 4; j++) e[j] = fmaxf(e[j], 0.f);
            }
            if (CHALF) {
                __half* C = (__half*)Cv;
                *reinterpret_cast<__half2*>(&C[(long long)row0 * N + col]) =
                    __floats2half2_rn(e[0], e[1]);
                *reinterpret_cast<__half2*>(&C[(long long)(row0 + 8) * N + col]) =
                    __floats2half2_rn(e[2], e[3]);
            } else {
                float* C = (float*)Cv;
                *reinterpret_cast<float2*>(&C[(long long)row0 * N + col]) =
                    make_float2(e[0], e[1]);
                *reinterpret_cast<float2*>(&C[(long long)(row0 + 8) * N + col]) =
                    make_float2(e[2], e[3]);
            }
        }
    }
}

template<int BTRANS, int CHALF>
__global__ __launch_bounds__(256, 2)
void hgemm_k(const __half* __restrict__ A, const __half* __restrict__ B,
             const float* __restrict__ bias, void* __restrict__ C,
             int N, int K, long long sA, long long sB, long long sC,
             float alpha, int relu, int causalSkip, int causalKlim)
{
    int rowStart = blockIdx.y * 128;
    int colStart = blockIdx.x * 128;
    if (causalSkip && rowStart + 127 < colStart) return;
    int z = blockIdx.z;
    A += (long long)z * sA;
    B += (long long)z * sB;
    C = (void*)((char*)C + (long long)z * sC * (CHALF ? 2 : 4));
    int Keff = K;
    if (causalKlim) { int kl = rowStart + 128; if (kl < Keff) Keff = kl; }
    hg_body<BTRANS, CHALF>(A, B, bias, C, N, K, rowStart, colStart, Keff, alpha, relu);
}

// fused 5-way projection: z in {q,k,v,k2,v2}; A = x16 (z<3) else kv16.
__global__ __launch_bounds__(256, 2)
void hg_proj5(const __half* __restrict__ x16, const __half* __restrict__ kv16,
              const __half* __restrict__ wt,
              const float* __restrict__ b0, const float* __restrict__ b1,
              const float* __restrict__ b2, const float* __restrict__ b3,
              const float* __restrict__ b4, __half* __restrict__ qkv)
{
    int z = blockIdx.z;
    const __half* A = (z < 3) ? x16 : kv16;
    const __half* B = wt + (long long)z * EE * EE;
    const float* bias = (z == 0) ? b0 : (z == 1) ? b1 : (z == 2) ? b2 : (z == 3) ? b3 : b4;
    __half* C = qkv + (long long)z * MM * EE;
    hg_body<0, 1>(A, B, bias, C, EE, EE, blockIdx.y * 128, blockIdx.x * 128, EE,
                  1.0f, 0);
}

// ---------------- fp32 -> fp16 convert ----------------
__global__ void cvt_h(const float4* __restrict__ S, __half2* __restrict__ D, int n4)
{
    int i = blockIdx.x * blockDim.x + threadIdx.x;
    if (i < n4) {
        float4 v = S[i];
        D[2 * i]     = __floats2half2_rn(v.x, v.y);
        D[2 * i + 1] = __floats2half2_rn(v.z, v.w);
    }
}

// ---------------- Weight transpose+convert: D[C,R]h = S[R,C]^T ----------------
__global__ void transp_h(const float* __restrict__ S, __half* __restrict__ D,
                         int R, int C)
{
    __shared__ float tb[32][33];
    int r0 = blockIdx.x * 32, c0 = blockIdx.y * 32;
    int tx = threadIdx.x & 31, ty = threadIdx.x >> 5;
    #pragma unroll
    for (int i = 0; i < 32; i += 8)
        tb[ty + i][tx] = S[(long long)(r0 + ty + i) * C + c0 + tx];
    __syncthreads();
    #pragma unroll
    for (int i = 0; i < 32; i += 8)
        D[(long long)(c0 + ty + i) * R + r0 + tx] = __float2half_rn(tb[tx][ty + i]);
}
__global__ void transp6_h(const float* __restrict__ s0, const float* __restrict__ s1,
                          const float* __restrict__ s2, const float* __restrict__ s3,
                          const float* __restrict__ s4, const float* __restrict__ s5,
                          __half* __restrict__ D)
{
    __shared__ float tb[32][33];
    int z = blockIdx.z;
    const float* S = (z==0)?s0:(z==1)?s1:(z==2)?s2:(z==3)?s3:(z==4)?s4:s5;
    __half* Dz = D + (long long)z * EE * EE;
    int r0 = blockIdx.x * 32, c0 = blockIdx.y * 32;
    int tx = threadIdx.x & 31, ty = threadIdx.x >> 5;
    #pragma unroll
    for (int i = 0; i < 32; i += 8)
        tb[ty + i][tx] = S[(long long)(r0 + ty + i) * EE + c0 + tx];
    __syncthreads();
    #pragma unroll
    for (int i = 0; i < 32; i += 8)
        Dz[(long long)(c0 + ty + i) * EE + r0 + tx] = __float2half_rn(tb[tx][ty + i]);
}

// ---------------- Softmax: fp32 scores -> fp16 probs ----------------
// Causal: mask j>=len; store zeros up to padded diagonal block only.
__global__ void softmax_rows(const float* __restrict__ P, __half* __restrict__ O,
                             int S, int causal)
{
    long long z = blockIdx.y;
    int i = blockIdx.x;
    const float* row = P + (z * S + i) * (long long)S;
    __half* orow = O + (z * S + i) * (long long)S;
    int len = causal ? (i + 1) : S;
    int lenPad = causal ? (((i >> 7) + 1) << 7) : S;

    int c0 = threadIdx.x * 4, c1 = c0 + 1024;
    float4 u0 = *reinterpret_cast<const float4*>(&row[c0]);
    float4 u1 = *reinterpret_cast<const float4*>(&row[c1]);
    float va[8] = {u0.x, u0.y, u0.z, u0.w, u1.x, u1.y, u1.z, u1.w};

    float mx = -INFINITY;
    #pragma unroll
    for (int e = 0; e < 4; e++) {
        if (c0 + e >= len) va[e] = -INFINITY;
        mx = fmaxf(mx, va[e]);
    }
    #pragma unroll
    for (int e = 0; e < 4; e++) {
        if (c1 + e >= len) va[4 + e] = -INFINITY;
        mx = fmaxf(mx, va[4 + e]);
    }
    mx = blockMax(mx);

    float s = 0.f;
    #pragma unroll
    for (int e = 0; e < 8; e++) { va[e] = expf(va[e] - mx); s += va[e]; }
    s = blockSum(s);
    float inv = 1.f / s;
    #pragma unroll
    for (int e = 0; e < 8; e++) va[e] *= inv;

    if (c0 < lenPad) {
        *reinterpret_cast<__half2*>(&orow[c0])     = __floats2half2_rn(va[0], va[1]);
        *reinterpret_cast<__half2*>(&orow[c0 + 2]) = __floats2half2_rn(va[2], va[3]);
    }
    if (c1 < lenPad) {
        *reinterpret_cast<__half2*>(&orow[c1])     = __floats2half2_rn(va[4], va[5]);
        *reinterpret_cast<__half2*>(&orow[c1 + 2]) = __floats2half2_rn(va[6], va[7]);
    }
}

// ---------------- Fused residual-add + LayerNorm (+ optional fp16 copy) ------
__global__ void add_ln(const float* __restrict__ X, const float* __restrict__ Hh,
                       const float* __restrict__ g, const float* __restrict__ b,
                       float* __restrict__ Y, __half* __restrict__ Yh)
{
    long long row = blockIdx.x;
    const float* x = X + row * EE;
    const float* h = Hh + row * EE;
    float* y = Y + row * EE;
    int tid = threadIdx.x;

    float v[3];
    float s = 0.f;
    #pragma unroll
    for (int k = 0; k < 3; k++) {
        int c = tid + k * 256;
        v[k] = x[c] + h[c];
        s += v[k];
    }
    s = blockSum(s);
    float mean = s * (1.0f / EE);

    float q = 0.f;
    #pragma unroll
    for (int k = 0; k < 3; k++) { float d = v[k] - mean; q += d * d; }
    q = blockSum(q);
    float inv = rsqrtf(q * (1.0f / EE) + LN_EPS);

    #pragma unroll
    for (int k = 0; k < 3; k++) {
        int c = tid + k * 256;
        float yv = (v[k] - mean) * inv * g[c] + b[c];
        y[c] = yv;
        if (Yh) Yh[row * EE + c] = __float2half_rn(yv);
    }
}

// ---------------- Orchestration ----------------
extern "C" void kernel_launch(void* const* d_in, const int* in_sizes, int n_in,
                              void* d_out, int out_size)
{
    const float* x     = (const float*)d_in[0];
    const float* kv    = (const float*)d_in[1];
    const float* wq_w  = (const float*)d_in[2];
    const float* wq_b  = (const float*)d_in[3];
    const float* wk_w  = (const float*)d_in[4];
    const float* wk_b  = (const float*)d_in[5];
    const float* wv_w  = (const float*)d_in[6];
    const float* wv_b  = (const float*)d_in[7];
    const float* ln1_g = (const float*)d_in[8];
    const float* ln1_b = (const float*)d_in[9];
    const float* wq2_w = (const float*)d_in[10];
    const float* wq2_b = (const float*)d_in[11];
    const float* wk2_w = (const float*)d_in[12];
    const float* wk2_b = (const float*)d_in[13];
    const float* wv2_w = (const float*)d_in[14];
    const float* wv2_b = (const float*)d_in[15];
    const float* ln2_g = (const float*)d_in[16];
    const float* ln2_b = (const float*)d_in[17];
    const float* mlp_w1= (const float*)d_in[18];
    const float* mlp_b1= (const float*)d_in[19];
    const float* mlp_w2= (const float*)d_in[20];
    const float* mlp_b2= (const float*)d_in[21];
    const float* ln3_g = (const float*)d_in[22];
    const float* ln3_b = (const float*)d_in[23];
    float* out = (float*)d_out;

    __half *qkv, *x16, *kv16, *x1h, *x2h, *hh16, *p16, *wt;
    float *sc, *t, *x1, *x2;
    cudaGetSymbolAddress((void**)&qkv,  g_qkv16);
    cudaGetSymbolAddress((void**)&x16,  g_x16);
    cudaGetSymbolAddress((void**)&kv16, g_kv16);
    cudaGetSymbolAddress((void**)&x1h,  g_x1h);
    cudaGetSymbolAddress((void**)&x2h,  g_x2h);
    cudaGetSymbolAddress((void**)&hh16, g_hh16);
    cudaGetSymbolAddress((void**)&p16,  g_p16);
    cudaGetSymbolAddress((void**)&wt,   g_wt16);
    cudaGetSymbolAddress((void**)&sc,   g_sc);
    cudaGetSymbolAddress((void**)&t,    g_t);
    cudaGetSymbolAddress((void**)&x1,   g_x1);
    cudaGetSymbolAddress((void**)&x2,   g_x2);

    cudaFuncSetAttribute(hgemm_k<0,0>, cudaFuncAttributeMaxDynamicSharedMemorySize, DSM);
    cudaFuncSetAttribute(hgemm_k<0,1>, cudaFuncAttributeMaxDynamicSharedMemorySize, DSM);
    cudaFuncSetAttribute(hgemm_k<1,0>, cudaFuncAttributeMaxDynamicSharedMemorySize, DSM);
    cudaFuncSetAttribute(hg_proj5,     cudaFuncAttributeMaxDynamicSharedMemorySize, DSM);

    __half* q16 = qkv;
    __half* k16 = qkv + 1LL*MM*EE;
    __half* v16 = qkv + 2LL*MM*EE;
    __half* k2  = qkv + 3LL*MM*EE;
    __half* v2  = qkv + 4LL*MM*EE;
    __half* wq2T = wt + 5LL*EE*EE;
    __half* w1T  = wt + 6LL*EE*EE;
    __half* w2T  = wt + 6LL*EE*EE + (long long)EE*HH;

    const float scale = 1.0f / sqrtf((float)EE);
    const long long SE  = (long long)SS * EE;
    const long long SSS = (long long)SS * SS;

    dim3 b256(256);
    dim3 gProj(EE / 128, MM / 128, 1);       // (6,128)
    dim3 gProj5(EE / 128, MM / 128, 5);      // (6,128,5)
    dim3 gScore(SS / 128, SS / 128, BB);     // (16,16,8)
    dim3 gPV(EE / 128, SS / 128, BB);        // (6,16,8)
    dim3 gMlp1(HH / 128, MM / 128, 1);       // (24,128)
    dim3 gSm(SS, BB);
    dim3 gLn(MM);

    // --- one-time conversions ---
    int n4 = MM * EE / 4;
    cvt_h<<<(n4 + 255) / 256, b256>>>((const float4*)x,  (__half2*)x16,  n4);
    cvt_h<<<(n4 + 255) / 256, b256>>>((const float4*)kv, (__half2*)kv16, n4);
    transp6_h<<<dim3(24, 24, 6), b256>>>(wq_w, wk_w, wv_w, wk2_w, wv2_w, wq2_w, wt);
    transp_h<<<dim3(EE/32, HH/32), b256>>>(mlp_w1, w1T, EE, HH);
    transp_h<<<dim3(HH/32, EE/32), b256>>>(mlp_w2, w2T, HH, EE);

    // --- all 5 input projections in one launch ---
    hg_proj5<<<gProj5, b256, DSM>>>(x16, kv16, wt, wq_b, wk_b, wv_b, wk2_b, wv2_b, qkv);

    // --- causal self-attention ---
    hgemm_k<0,0><<<gScore, b256, DSM>>>(q16, k16, nullptr, sc, SS, EE,
                                        SE, SE, SSS, scale, 0, 1, 0);
    softmax_rows<<<gSm, b256>>>(sc, p16, SS, 1);
    hgemm_k<1,0><<<gPV, b256, DSM>>>(p16, v16, nullptr, t, EE, SS,
                                     SSS, SE, SE, 1.0f, 0, 0, 1);
    add_ln<<<gLn, b256>>>(x, t, ln1_g, ln1_b, x1, x1h);

    // --- cross-attention ---
    hgemm_k<0,1><<<gProj, b256, DSM>>>(x1h, wq2T, wq2_b, q16, EE, EE,
                                       0, 0, 0, 1.0f, 0, 0, 0);
    hgemm_k<0,0><<<gScore, b256, DSM>>>(q16, k2, nullptr, sc, SS, EE,
                                        SE, SE, SSS, scale, 0, 0, 0);
    softmax_rows<<<gSm, b256>>>(sc, p16, SS, 0);
    hgemm_k<1,0><<<gPV, b256, DSM>>>(p16, v2, nullptr, t, EE, SS,
                                     SSS, SE, SE, 1.0f, 0, 0, 0);
    add_ln<<<gLn, b256>>>(x1, t, ln2_g, ln2_b, x2, x2h);

    // --- MLP (ReLU after both linears) ---
    hgemm_k<0,1><<<gMlp1, b256, DSM>>>(x2h, w1T, mlp_b1, hh16, HH, EE,
                                       0, 0, 0, 1.0f, 1, 0, 0);
    hgemm_k<0,0><<<gProj, b256, DSM>>>(hh16, w2T, mlp_b2, t, EE, HH,
                                       0, 0, 0, 1.0f, 1, 0, 0);
    add_ln<<<gLn, b256>>>(x2, t, ln3_g, ln3_b, out, nullptr);
}

// round 10
// speedup vs baseline: 7.7079x; 1.0155x over previous
#include <cuda_runtime.h>
#include <cuda_fp16.h>
#include <math.h>
#include <stdint.h>

// ---------------- Problem constants ----------------
#define BB 8
#define SS 2048
#define EE 768
#define HH 3072          // R*E
#define MM (BB*SS)       // 16384
#define LN_EPS 1e-5f

// fp16 GEMM tiling: CTA 128x128, BK=64, 256 thr, 8 warps of 64x32
#define HBK 64
#define STAGE_BYTES 32768            // A 16KB + B 16KB per stage
#define DSM (2*STAGE_BYTES)          // 64KB dynamic smem

// ---------------- Scratch (device globals; no allocs allowed) ----------------
__device__ __half g_qkv16[5LL*MM*EE];   // 0=q/q2, 1=k, 2=v, 3=k2, 4=v2
__device__ __half g_x16[MM*EE];
__device__ __half g_kv16[MM*EE];
__device__ __half g_x1h[MM*EE];
__device__ __half g_x2h[MM*EE];
__device__ __half g_hh16[(long long)MM*HH];
__device__ __half g_p16[(long long)BB*SS*SS];
__device__ __half g_wt16[6*EE*EE + 2*EE*HH];  // wqT,wkT,wvT,wk2T,wv2T,wq2T,w1T,w2T
__device__ float  g_t[MM*EE];
__device__ float  g_x1[MM*EE];
__device__ float  g_x2[MM*EE];

// ---------------- Reductions ----------------
__device__ __forceinline__ float warpSum(float v) {
    #pragma unroll
    for (int o = 16; o > 0; o >>= 1) v += __shfl_xor_sync(0xffffffffu, v, o);
    return v;
}
__device__ __forceinline__ float warpMax(float v) {
    #pragma unroll
    for (int o = 16; o > 0; o >>= 1) v = fmaxf(v, __shfl_xor_sync(0xffffffffu, v, o));
    return v;
}
__device__ float blockSum(float v) {
    __shared__ float sh[32];
    int lane = threadIdx.x & 31, w = threadIdx.x >> 5;
    v = warpSum(v);
    if (lane == 0) sh[w] = v;
    __syncthreads();
    int nw = (blockDim.x + 31) >> 5;
    float r = (threadIdx.x < nw) ? sh[threadIdx.x] : 0.f;
    if (w == 0) r = warpSum(r);
    if (threadIdx.x == 0) sh[0] = r;
    __syncthreads();
    r = sh[0];
    __syncthreads();
    return r;
}
__device__ float blockMax(float v) {
    __shared__ float sh[32];
    int lane = threadIdx.x & 31, w = threadIdx.x >> 5;
    v = warpMax(v);
    if (lane == 0) sh[w] = v;
    __syncthreads();
    int nw = (blockDim.x + 31) >> 5;
    float r = (threadIdx.x < nw) ? sh[threadIdx.x] : -INFINITY;
    if (w == 0) r = warpMax(r);
    if (threadIdx.x == 0) sh[0] = r;
    __syncthreads();
    r = sh[0];
    __syncthreads();
    return r;
}

// ---------------- PTX helpers ----------------
__device__ __forceinline__ void cp16(uint32_t dst, const void* src) {
    asm volatile("cp.async.cg.shared.global [%0], [%1], 16;\n" :: "r"(dst), "l"(src));
}
__device__ __forceinline__ void cp_commit() { asm volatile("cp.async.commit_group;\n"); }
__device__ __forceinline__ void cp_wait0()  { asm volatile("cp.async.wait_group 0;\n"); }
__device__ __forceinline__ void cp_wait1()  { asm volatile("cp.async.wait_group 1;\n"); }

__device__ __forceinline__ void mma_f16(float* d, const uint32_t* a,
                                        const uint32_t* b, const float* c) {
    asm volatile(
        "mma.sync.aligned.m16n8k16.row.col.f32.f16.f16.f32 "
        "{%0,%1,%2,%3}, {%4,%5,%6,%7}, {%8,%9}, {%10,%11,%12,%13};\n"
        : "=f"(d[0]), "=f"(d[1]), "=f"(d[2]), "=f"(d[3])
        : "r"(a[0]), "r"(a[1]), "r"(a[2]), "r"(a[3]),
          "r"(b[0]), "r"(b[1]),
          "f"(c[0]), "f"(c[1]), "f"(c[2]), "f"(c[3]));
}
__device__ __forceinline__ void ldsm4(uint32_t* r, uint32_t addr) {
    asm volatile("ldmatrix.sync.aligned.m8n8.x4.shared.b16 {%0,%1,%2,%3}, [%4];\n"
        : "=r"(r[0]), "=r"(r[1]), "=r"(r[2]), "=r"(r[3]) : "r"(addr));
}
__device__ __forceinline__ void ldsm4t(uint32_t* r, uint32_t addr) {
    asm volatile("ldmatrix.sync.aligned.m8n8.x4.trans.shared.b16 {%0,%1,%2,%3}, [%4];\n"
        : "=r"(r[0]), "=r"(r[1]), "=r"(r[2]), "=r"(r[3]) : "r"(addr));
}

// ---------------- fp16 GEMM body ----------------
// NT (BTRANS=0): C[M,N] = A[M,K] @ B[N,K]^T ; btrans (BTRANS=1): B stored [K,N].
// A smem: 128 rows x 64 halves (128B), 16B chunk c of row m at (c ^ (m&7)).
// B NT smem: same geometry (rows = n). B trans smem: 64 k-rows x 128 halves
// (256B), chunk nc of row k at (nc ^ (k&7)).
template<int BTRANS, int CHALF>
__device__ void hg_body(const __half* __restrict__ A, const __half* __restrict__ B,
                        const float* __restrict__ bias, void* __restrict__ Cv,
                        int N, int K, int rowStart, int colStart, int Keff,
                        float alpha, int relu)
{
    extern __shared__ char dynsm[];
    uint32_t smBase = (uint32_t)__cvta_generic_to_shared(dynsm);

    int tid = threadIdx.x, lane = tid & 31, wid = tid >> 5;
    int wm = (wid >> 2) * 64, wn = (wid & 3) * 32;
    int g = lane >> 2, tg = lane & 3;
    int T = Keff / HBK;

    auto loadTile = [&](int kt, int s) {
        uint32_t aB = smBase + s * STAGE_BYTES;
        uint32_t bB = aB + 16384;
        #pragma unroll
        for (int i = 0; i < 4; i++) {
            int idx = tid + i * 256;             // 1024 chunks
            int m = idx >> 3, c = idx & 7;
            cp16(aB + m * 128 + ((c ^ (m & 7)) << 4),
                 &A[(long long)(rowStart + m) * K + kt + c * 8]);
        }
        if (!BTRANS) {
            #pragma unroll
            for (int i = 0; i < 4; i++) {
                int idx = tid + i * 256;
                int n = idx >> 3, c = idx & 7;
                cp16(bB + n * 128 + ((c ^ (n & 7)) << 4),
                     &B[(long long)(colStart + n) * K + kt + c * 8]);
            }
        } else {
            #pragma unroll
            for (int i = 0; i < 4; i++) {
                int idx = tid + i * 256;
                int k = idx >> 4, nc = idx & 15;
                cp16(bB + k * 256 + ((nc ^ (k & 7)) << 4),
                     &B[(long long)(kt + k) * N + colStart + nc * 8]);
            }
        }
        cp_commit();
    };

    float acc[4][4][4] = {};
    loadTile(0, 0);
    int buf = 0;
    for (int it = 0; it < T; it++) {
        if (it + 1 < T) { loadTile((it + 1) * HBK, buf ^ 1); cp_wait1(); }
        else cp_wait0();
        __syncthreads();

        uint32_t aT = smBase + buf * STAGE_BYTES;
        uint32_t bT = aT + 16384;
        #pragma unroll
        for (int ks = 0; ks < 4; ks++) {
            uint32_t afr[4][4], bfr[4][2];
            #pragma unroll
            for (int mi = 0; mi < 4; mi++) {
                int m = wm + mi * 16 + (lane & 15);
                int c = 2 * ks + (lane >> 4);
                ldsm4(afr[mi], aT + m * 128 + ((c ^ (m & 7)) << 4));
            }
            if (!BTRANS) {
                #pragma unroll
                for (int h = 0; h < 2; h++) {
                    int n = wn + h * 16 + (lane & 7) + ((lane >> 4) & 1) * 8;
                    int c = 2 * ks + ((lane >> 3) & 1);
                    ldsm4(&bfr[2 * h][0], bT + n * 128 + ((c ^ (n & 7)) << 4));
                }
            } else {
                #pragma unroll
                for (int h = 0; h < 2; h++) {
                    int k = ks * 16 + (lane & 7) + ((lane >> 3) & 1) * 8;
                    int nc = (wn >> 3) + h * 2 + ((lane >> 4) & 1);
                    ldsm4t(&bfr[2 * h][0], bT + k * 256 + ((nc ^ (k & 7)) << 4));
                }
            }
            #pragma unroll
            for (int mi = 0; mi < 4; mi++)
                #pragma unroll
                for (int ni = 0; ni < 4; ni++)
                    mma_f16(acc[mi][ni], afr[mi], bfr[ni], acc[mi][ni]);
        }
        __syncthreads();
        buf ^= 1;
    }

    // Epilogue
    #pragma unroll
    for (int mi = 0; mi < 4; mi++) {
        int row0 = rowStart + wm + mi * 16 + g;
        #pragma unroll
        for (int ni = 0; ni < 4; ni++) {
            int col = colStart + wn + ni * 8 + tg * 2;
            float e[4];
            #pragma unroll
            for (int j = 0; j < 4; j++) e[j] = acc[mi][ni][j] * alpha;
            if (bias) {
                float b0 = bias[col], b1 = bias[col + 1];
                e[0] += b0; e[1] += b1; e[2] += b0; e[3] += b1;
            }
            if (relu) {
                #pragma unroll
                for (int j = 0; j < 4; j++) e[j] = fmaxf(e[j], 0.f);
            }
            if (CHALF) {
                __half* C = (__half*)Cv;
                *reinterpret_cast<__half2*>(&C[(long long)row0 * N + col]) =
                    __floats2half2_rn(e[0], e[1]);
                *reinterpret_cast<__half2*>(&C[(long long)(row0 + 8) * N + col]) =
                    __floats2half2_rn(e[2], e[3]);
            } else {
                float* C = (float*)Cv;
                *reinterpret_cast<float2*>(&C[(long long)row0 * N + col]) =
                    make_float2(e[0], e[1]);
                *reinterpret_cast<float2*>(&C[(long long)(row0 + 8) * N + col]) =
                    make_float2(e[2], e[3]);
            }
        }
    }
}

template<int BTRANS, int CHALF>
__global__ __launch_bounds__(256, 2)
void hgemm_k(const __half* __restrict__ A, const __half* __restrict__ B,
             const float* __restrict__ bias, void* __restrict__ C,
             int N, int K, long long sA, long long sB, long long sC,
             float alpha, int relu, int causalSkip, int causalKlim)
{
    int rowStart = blockIdx.y * 128;
    int colStart = blockIdx.x * 128;
    if (causalSkip && rowStart + 127 < colStart) return;
    int z = blockIdx.z;
    A += (long long)z * sA;
    B += (long long)z * sB;
    C = (void*)((char*)C + (long long)z * sC * (CHALF ? 2 : 4));
    int Keff = K;
    if (causalKlim) { int kl = rowStart + 128; if (kl < Keff) Keff = kl; }
    hg_body<BTRANS, CHALF>(A, B, bias, C, N, K, rowStart, colStart, Keff, alpha, relu);
}

// fused 5-way projection: z in {q,k,v,k2,v2}; A = x16 (z<3) else kv16.
__global__ __launch_bounds__(256, 2)
void hg_proj5(const __half* __restrict__ x16, const __half* __restrict__ kv16,
              const __half* __restrict__ wt,
              const float* __restrict__ b0, const float* __restrict__ b1,
              const float* __restrict__ b2, const float* __restrict__ b3,
              const float* __restrict__ b4, __half* __restrict__ qkv)
{
    int z = blockIdx.z;
    const __half* A = (z < 3) ? x16 : kv16;
    const __half* B = wt + (long long)z * EE * EE;
    const float* bias = (z == 0) ? b0 : (z == 1) ? b1 : (z == 2) ? b2 : (z == 3) ? b3 : b4;
    __half* C = qkv + (long long)z * MM * EE;
    hg_body<0, 1>(A, B, bias, C, EE, EE, blockIdx.y * 128, blockIdx.x * 128, EE,
                  1.0f, 0);
}

// ---------------- fp32 -> fp16 convert (two tensors in one launch) ----------
__global__ void cvt2_h(const float4* __restrict__ S0, const float4* __restrict__ S1,
                       __half2* __restrict__ D0, __half2* __restrict__ D1, int n4)
{
    const float4* S = blockIdx.y ? S1 : S0;
    __half2* D = blockIdx.y ? D1 : D0;
    int i = blockIdx.x * blockDim.x + threadIdx.x;
    if (i < n4) {
        float4 v = S[i];
        D[2 * i]     = __floats2half2_rn(v.x, v.y);
        D[2 * i + 1] = __floats2half2_rn(v.z, v.w);
    }
}

// ---------------- Weight transpose+convert: D[C,R]h = S[R,C]^T ----------------
__global__ void transp_h(const float* __restrict__ S, __half* __restrict__ D,
                         int R, int C)
{
    __shared__ float tb[32][33];
    int r0 = blockIdx.x * 32, c0 = blockIdx.y * 32;
    int tx = threadIdx.x & 31, ty = threadIdx.x >> 5;
    #pragma unroll
    for (int i = 0; i < 32; i += 8)
        tb[ty + i][tx] = S[(long long)(r0 + ty + i) * C + c0 + tx];
    __syncthreads();
    #pragma unroll
    for (int i = 0; i < 32; i += 8)
        D[(long long)(c0 + ty + i) * R + r0 + tx] = __float2half_rn(tb[tx][ty + i]);
}
__global__ void transp6_h(const float* __restrict__ s0, const float* __restrict__ s1,
                          const float* __restrict__ s2, const float* __restrict__ s3,
                          const float* __restrict__ s4, const float* __restrict__ s5,
                          __half* __restrict__ D)
{
    __shared__ float tb[32][33];
    int z = blockIdx.z;
    const float* S = (z==0)?s0:(z==1)?s1:(z==2)?s2:(z==3)?s3:(z==4)?s4:s5;
    __half* Dz = D + (long long)z * EE * EE;
    int r0 = blockIdx.x * 32, c0 = blockIdx.y * 32;
    int tx = threadIdx.x & 31, ty = threadIdx.x >> 5;
    #pragma unroll
    for (int i = 0; i < 32; i += 8)
        tb[ty + i][tx] = S[(long long)(r0 + ty + i) * EE + c0 + tx];
    __syncthreads();
    #pragma unroll
    for (int i = 0; i < 32; i += 8)
        Dz[(long long)(c0 + ty + i) * EE + r0 + tx] = __float2half_rn(tb[tx][ty + i]);
}

// ---------------- Softmax: fp16 scores -> fp16 probs, in place --------------
// 256 thr, 8 halves each. Causal: mask j>=len; store up to padded diag block.
__global__ void softmax16(__half* __restrict__ P, int S, int causal)
{
    long long z = blockIdx.y;
    int i = blockIdx.x;
    __half* row = P + (z * S + i) * (long long)S;
    int len = causal ? (i + 1) : S;
    int lenPad = causal ? (((i >> 7) + 1) << 7) : S;

    int c0 = threadIdx.x * 8;
    uint4 raw = *reinterpret_cast<const uint4*>(&row[c0]);
    __half2 hp[4];
    hp[0] = *reinterpret_cast<__half2*>(&raw.x);
    hp[1] = *reinterpret_cast<__half2*>(&raw.y);
    hp[2] = *reinterpret_cast<__half2*>(&raw.z);
    hp[3] = *reinterpret_cast<__half2*>(&raw.w);

    float va[8];
    #pragma unroll
    for (int p = 0; p < 4; p++) {
        float2 f = __half22float2(hp[p]);
        va[2 * p] = f.x; va[2 * p + 1] = f.y;
    }
    float mx = -INFINITY;
    #pragma unroll
    for (int e = 0; e < 8; e++) {
        if (c0 + e >= len) va[e] = -INFINITY;
        mx = fmaxf(mx, va[e]);
    }
    mx = blockMax(mx);

    float s = 0.f;
    #pragma unroll
    for (int e = 0; e < 8; e++) { va[e] = expf(va[e] - mx); s += va[e]; }
    s = blockSum(s);
    float inv = 1.f / s;
    #pragma unroll
    for (int e = 0; e < 8; e++) va[e] *= inv;

    if (c0 < lenPad) {
        uint4 o;
        __half2 o0 = __floats2half2_rn(va[0], va[1]);
        __half2 o1 = __floats2half2_rn(va[2], va[3]);
        __half2 o2 = __floats2half2_rn(va[4], va[5]);
        __half2 o3 = __floats2half2_rn(va[6], va[7]);
        o.x = *reinterpret_cast<uint32_t*>(&o0);
        o.y = *reinterpret_cast<uint32_t*>(&o1);
        o.z = *reinterpret_cast<uint32_t*>(&o2);
        o.w = *reinterpret_cast<uint32_t*>(&o3);
        *reinterpret_cast<uint4*>(&row[c0]) = o;
    }
}

// ---------------- Fused residual-add + LayerNorm (192 thr, float4) ----------
__global__ void add_ln(const float* __restrict__ X, const float* __restrict__ Hh,
                       const float* __restrict__ g, const float* __restrict__ b,
                       float* __restrict__ Y, __half* __restrict__ Yh)
{
    long long row = blockIdx.x;
    const float* x = X + row * EE;
    const float* h = Hh + row * EE;
    float* y = Y + row * EE;
    int c = threadIdx.x * 4;

    float4 xv = *reinterpret_cast<const float4*>(&x[c]);
    float4 hv = *reinterpret_cast<const float4*>(&h[c]);
    float v[4] = {xv.x + hv.x, xv.y + hv.y, xv.z + hv.z, xv.w + hv.w};

    float s = v[0] + v[1] + v[2] + v[3];
    s = blockSum(s);
    float mean = s * (1.0f / EE);

    float q = 0.f;
    #pragma unroll
    for (int j = 0; j < 4; j++) { float d = v[j] - mean; q += d * d; }
    q = blockSum(q);
    float inv = rsqrtf(q * (1.0f / EE) + LN_EPS);

    float4 gv = *reinterpret_cast<const float4*>(&g[c]);
    float4 bv = *reinterpret_cast<const float4*>(&b[c]);
    float o[4];
    o[0] = (v[0] - mean) * inv * gv.x + bv.x;
    o[1] = (v[1] - mean) * inv * gv.y + bv.y;
    o[2] = (v[2] - mean) * inv * gv.z + bv.z;
    o[3] = (v[3] - mean) * inv * gv.w + bv.w;
    *reinterpret_cast<float4*>(&y[c]) = make_float4(o[0], o[1], o[2], o[3]);
    if (Yh) {
        __half2 h0 = __floats2half2_rn(o[0], o[1]);
        __half2 h1 = __floats2half2_rn(o[2], o[3]);
        uint2 u;
        u.x = *reinterpret_cast<uint32_t*>(&h0);
        u.y = *reinterpret_cast<uint32_t*>(&h1);
        *reinterpret_cast<uint2*>(&Yh[row * EE + c]) = u;
    }
}

// ---------------- Orchestration ----------------
extern "C" void kernel_launch(void* const* d_in, const int* in_sizes, int n_in,
                              void* d_out, int out_size)
{
    const float* x     = (const float*)d_in[0];
    const float* kv    = (const float*)d_in[1];
    const float* wq_w  = (const float*)d_in[2];
    const float* wq_b  = (const float*)d_in[3];
    const float* wk_w  = (const float*)d_in[4];
    const float* wk_b  = (const float*)d_in[5];
    const float* wv_w  = (const float*)d_in[6];
    const float* wv_b  = (const float*)d_in[7];
    const float* ln1_g = (const float*)d_in[8];
    const float* ln1_b = (const float*)d_in[9];
    const float* wq2_w = (const float*)d_in[10];
    const float* wq2_b = (const float*)d_in[11];
    const float* wk2_w = (const float*)d_in[12];
    const float* wk2_b = (const float*)d_in[13];
    const float* wv2_w = (const float*)d_in[14];
    const float* wv2_b = (const float*)d_in[15];
    const float* ln2_g = (const float*)d_in[16];
    const float* ln2_b = (const float*)d_in[17];
    const float* mlp_w1= (const float*)d_in[18];
    const float* mlp_b1= (const float*)d_in[19];
    const float* mlp_w2= (const float*)d_in[20];
    const float* mlp_b2= (const float*)d_in[21];
    const float* ln3_g = (const float*)d_in[22];
    const float* ln3_b = (const float*)d_in[23];
    float* out = (float*)d_out;

    __half *qkv, *x16, *kv16, *x1h, *x2h, *hh16, *p16, *wt;
    float *t, *x1, *x2;
    cudaGetSymbolAddress((void**)&qkv,  g_qkv16);
    cudaGetSymbolAddress((void**)&x16,  g_x16);
    cudaGetSymbolAddress((void**)&kv16, g_kv16);
    cudaGetSymbolAddress((void**)&x1h,  g_x1h);
    cudaGetSymbolAddress((void**)&x2h,  g_x2h);
    cudaGetSymbolAddress((void**)&hh16, g_hh16);
    cudaGetSymbolAddress((void**)&p16,  g_p16);
    cudaGetSymbolAddress((void**)&wt,   g_wt16);
    cudaGetSymbolAddress((void**)&t,    g_t);
    cudaGetSymbolAddress((void**)&x1,   g_x1);
    cudaGetSymbolAddress((void**)&x2,   g_x2);

    cudaFuncSetAttribute(hgemm_k<0,0>, cudaFuncAttributeMaxDynamicSharedMemorySize, DSM);
    cudaFuncSetAttribute(hgemm_k<0,1>, cudaFuncAttributeMaxDynamicSharedMemorySize, DSM);
    cudaFuncSetAttribute(hgemm_k<1,0>, cudaFuncAttributeMaxDynamicSharedMemorySize, DSM);
    cudaFuncSetAttribute(hg_proj5,     cudaFuncAttributeMaxDynamicSharedMemorySize, DSM);

    __half* q16 = qkv;
    __half* k16 = qkv + 1LL*MM*EE;
    __half* v16 = qkv + 2LL*MM*EE;
    __half* k2  = qkv + 3LL*MM*EE;
    __half* v2  = qkv + 4LL*MM*EE;
    __half* wq2T = wt + 5LL*EE*EE;
    __half* w1T  = wt + 6LL*EE*EE;
    __half* w2T  = wt + 6LL*EE*EE + (long long)EE*HH;

    const float scale = 1.0f / sqrtf((float)EE);
    const long long SE  = (long long)SS * EE;
    const long long SSS = (long long)SS * SS;

    dim3 b256(256), b192(192);
    dim3 gProj(EE / 128, MM / 128, 1);       // (6,128)
    dim3 gProj5(EE / 128, MM / 128, 5);      // (6,128,5)
    dim3 gScore(SS / 128, SS / 128, BB);     // (16,16,8)
    dim3 gPV(EE / 128, SS / 128, BB);        // (6,16,8)
    dim3 gMlp1(HH / 128, MM / 128, 1);       // (24,128)
    dim3 gSm(SS, BB);
    dim3 gLn(MM);

    // --- one-time conversions ---
    int n4 = MM * EE / 4;
    cvt2_h<<<dim3((n4 + 255) / 256, 2), b256>>>((const float4*)x, (const float4*)kv,
                                                (__half2*)x16, (__half2*)kv16, n4);
    transp6_h<<<dim3(24, 24, 6), b256>>>(wq_w, wk_w, wv_w, wk2_w, wv2_w, wq2_w, wt);
    transp_h<<<dim3(EE/32, HH/32), b256>>>(mlp_w1, w1T, EE, HH);
    transp_h<<<dim3(HH/32, EE/32), b256>>>(mlp_w2, w2T, HH, EE);

    // --- all 5 input projections in one launch ---
    hg_proj5<<<gProj5, b256, DSM>>>(x16, kv16, wt, wq_b, wk_b, wv_b, wk2_b, wv2_b, qkv);

    // --- causal self-attention (fp16 scores end-to-end) ---
    hgemm_k<0,1><<<gScore, b256, DSM>>>(q16, k16, nullptr, p16, SS, EE,
                                        SE, SE, SSS, scale, 0, 1, 0);
    softmax16<<<gSm, b256>>>(p16, SS, 1);
    hgemm_k<1,0><<<gPV, b256, DSM>>>(p16, v16, nullptr, t, EE, SS,
                                     SSS, SE, SE, 1.0f, 0, 0, 1);
    add_ln<<<gLn, b192>>>(x, t, ln1_g, ln1_b, x1, x1h);

    // --- cross-attention ---
    hgemm_k<0,1><<<gProj, b256, DSM>>>(x1h, wq2T, wq2_b, q16, EE, EE,
                                       0, 0, 0, 1.0f, 0, 0, 0);
    hgemm_k<0,1><<<gScore, b256, DSM>>>(q16, k2, nullptr, p16, SS, EE,
                                        SE, SE, SSS, scale, 0, 0, 0);
    softmax16<<<gSm, b256>>>(p16, SS, 0);
    hgemm_k<1,0><<<gPV, b256, DSM>>>(p16, v2, nullptr, t, EE, SS,
                                     SSS, SE, SE, 1.0f, 0, 0, 0);
    add_ln<<<gLn, b192>>>(x1, t, ln2_g, ln2_b, x2, x2h);

    // --- MLP (ReLU after both linears) ---
    hgemm_k<0,1><<<gMlp1, b256, DSM>>>(x2h, w1T, mlp_b1, hh16, HH, EE,
                                       0, 0, 0, 1.0f, 1, 0, 0);
    hgemm_k<0,0><<<gProj, b256, DSM>>>(hh16, w2T, mlp_b2, t, EE, HH,
                                       0, 0, 0, 1.0f, 1, 0, 0);
    add_ln<<<gLn, b192>>>(x2, t, ln3_g, ln3_b, out, nullptr);
}